// round 9
// baseline (speedup 1.0000x reference)
#include <cuda_runtime.h>
#include <cuda_fp16.h>
#include <cstdint>

#define M_TOTAL 32768
#define DHALF   256
#define D2      512
#define KCB     4096

#define BLK_M 128
#define BLK_N 128
#define NTILES  (KCB / BLK_N)       // 32
#define KSTAGES (D2 / 32)           // 16 k32-stages per n-tile
#define NSTAGES (NTILES * KSTAGES)  // 512

// smem: per split tile 128 rows x 80B (32 fp16 = 64B data + 16B pad)
#define ROW_BYTES   80
#define SPLIT_BYTES (128 * ROW_BYTES)            // 10240
#define STAGE_BYTES (4 * SPLIT_BYTES)            // A0,A1,B0,B1 = 40960
#define SRED_OFF    (2 * STAGE_BYTES)            // 81920 (2-deep ring)
#define SMEM_TOTAL  (SRED_OFF + BLK_M * 8 * 8)   // + 8KB keys = 90112

#define OUT_REAL_OFF 0
#define OUT_IMAG_OFF 8388608
#define OUT_LOSS_OFF 16777216
#define OUT_IDX_OFF  16777217

__device__ __align__(16) float g_cnorm[KCB];
__device__ int   g_prev[M_TOTAL];
__device__ int   g_idx[M_TOTAL];
__device__ float g_rowsum[M_TOTAL];
// 2-way fp16 splits, K-major [row][k 0..511]
__device__ __align__(16) __half g_zh[2][(size_t)M_TOTAL * D2];
__device__ __align__(16) __half g_ch[2][(size_t)KCB * D2];

// ---------------------------------------------------------------------------
__device__ __forceinline__ uint32_t smem_u32(const void* p) {
    uint32_t a;
    asm("{ .reg .u64 t; cvta.to.shared.u64 t, %1; cvt.u32.u64 %0, t; }"
        : "=r"(a) : "l"(p));
    return a;
}

__device__ __forceinline__ void cp16(uint32_t dst, const void* src) {
    asm volatile("cp.async.cg.shared.global [%0], [%1], 16;"
                 :: "r"(dst), "l"(src) : "memory");
}
#define CP_COMMIT() asm volatile("cp.async.commit_group;" ::: "memory")
#define CP_WAIT0()  asm volatile("cp.async.wait_group 0;" ::: "memory")

__device__ __forceinline__ void ldmatrix_x4(uint32_t* r, uint32_t addr) {
    asm volatile("ldmatrix.sync.aligned.m8n8.x4.shared.b16 {%0,%1,%2,%3}, [%4];"
                 : "=r"(r[0]), "=r"(r[1]), "=r"(r[2]), "=r"(r[3]) : "r"(addr));
}

__device__ __forceinline__ void mma_f16(float* d, const uint32_t* a,
                                        const uint32_t* b) {
    asm volatile(
        "mma.sync.aligned.m16n8k16.row.col.f32.f16.f16.f32 "
        "{%0,%1,%2,%3},{%4,%5,%6,%7},{%8,%9},{%0,%1,%2,%3};"
        : "+f"(d[0]), "+f"(d[1]), "+f"(d[2]), "+f"(d[3])
        : "r"(a[0]), "r"(a[1]), "r"(a[2]), "r"(a[3]), "r"(b[0]), "r"(b[1]));
}

// exact 2-way fp16 split: v = h0 + h1 (to ~2^-22 rel)
__device__ __forceinline__ void split2(float v, unsigned short& s0,
                                       unsigned short& s1) {
    __half h0 = __float2half_rn(v);
    __half h1 = __float2half_rn(v - __half2float(h0));
    s0 = __half_as_ushort(h0);
    s1 = __half_as_ushort(h1);
}

__device__ __forceinline__ float sig08(float x) {
    float x2 = x * x;
    // 0.8*sigmoid(x) = 0.4 + 0.8*x*p(x^2), odd Taylor to x^9 (|x| <= 1)
    float p = 2.1356922e-05f;
    p = fmaf(p, x2, -2.1081349e-04f);
    p = fmaf(p, x2,  2.0833334e-03f);
    p = fmaf(p, x2, -2.0833333e-02f);
    p = fmaf(p, x2,  0.25f);
    float s = fmaf(0.8f * x, p, 0.4f);
    if (fabsf(x) > 1.0f) s = 0.8f / (1.0f + __expf(-x));
    return s;
}

// ---------------------------------------------------------------------------
// Kernel 0: normalize prev_symbol_idx (int64 vs int32 sniff)
// ---------------------------------------------------------------------------
__global__ void prev_kernel(const void* __restrict__ p) {
    const long long* p64 = (const long long*)p;
    const int*       p32 = (const int*)p;
    bool is64 = true;
    for (int t = 0; t < 64; t++) {
        long long v = p64[t];
        if (v < 0 || v >= KCB) { is64 = false; break; }
    }
    int i = blockIdx.x * blockDim.x + threadIdx.x;
    if (i < M_TOTAL) g_prev[i] = is64 ? (int)p64[i] : p32[i];
}

// ---------------------------------------------------------------------------
// Kernel 1: cnorm[k] = ||codebook[k]||^2 (exact, f32)
// ---------------------------------------------------------------------------
__global__ void cnorm_kernel(const float* __restrict__ cb) {
    int warp = (blockIdx.x * blockDim.x + threadIdx.x) >> 5;
    int lane = threadIdx.x & 31;
    if (warp >= KCB) return;
    const float4* row = reinterpret_cast<const float4*>(cb + (size_t)warp * D2);
    float s = 0.f;
#pragma unroll
    for (int w = 0; w < 4; w++) {
        float4 v = row[lane + 32 * w];
        s += v.x * v.x + v.y * v.y + v.z * v.z + v.w * v.w;
    }
#pragma unroll
    for (int o = 16; o; o >>= 1) s += __shfl_xor_sync(0xffffffffu, s, o);
    if (lane == 0) g_cnorm[warp] = s;
}

// ---------------------------------------------------------------------------
// Split kernels: f32 -> 2x fp16 slices
// ---------------------------------------------------------------------------
__global__ void split_z_kernel(const float* __restrict__ zr,
                               const float* __restrict__ zi) {
    int g = blockIdx.x * blockDim.x + threadIdx.x;
    int m  = g >> 7;
    int k4 = (g & 127) * 4;
    float4 v = (k4 < DHALF)
        ? *reinterpret_cast<const float4*>(zr + (size_t)m * DHALF + k4)
        : *reinterpret_cast<const float4*>(zi + (size_t)m * DHALF + (k4 - DHALF));
    ushort4 o0, o1;
    split2(v.x, o0.x, o1.x);
    split2(v.y, o0.y, o1.y);
    split2(v.z, o0.z, o1.z);
    split2(v.w, o0.w, o1.w);
    size_t off = (size_t)m * D2 + k4;
    *reinterpret_cast<ushort4*>(&g_zh[0][off]) = o0;
    *reinterpret_cast<ushort4*>(&g_zh[1][off]) = o1;
}

__global__ void split_cb_kernel(const float* __restrict__ cb) {
    int g = blockIdx.x * blockDim.x + threadIdx.x;
    size_t off = (size_t)g * 4;
    float4 v = *reinterpret_cast<const float4*>(cb + off);
    ushort4 o0, o1;
    split2(v.x, o0.x, o1.x);
    split2(v.y, o0.y, o1.y);
    split2(v.z, o0.z, o1.z);
    split2(v.w, o0.w, o1.w);
    *reinterpret_cast<ushort4*>(&g_ch[0][off]) = o0;
    *reinterpret_cast<ushort4*>(&g_ch[1][off]) = o1;
}

// ---------------------------------------------------------------------------
// cp.async one k32-stage: 4 tiles x 128 rows x 64B; thread = one row, 16 cp16
// ---------------------------------------------------------------------------
__device__ __forceinline__ void stage_cp(uint32_t sbase, int buf, int m0,
                                         int s, int tid) {
    const int nt = s >> 4;
    const int kb = (s & 15) * 32;
    const uint32_t d = sbase + buf * STAGE_BYTES + tid * ROW_BYTES;
    const size_t aoff = (size_t)(m0 + tid) * D2 + kb;
    const size_t boff = (size_t)(nt * BLK_N + tid) * D2 + kb;
#pragma unroll
    for (int c = 0; c < 4; c++) {
        cp16(d + c * 16,                   &g_zh[0][aoff + c * 8]);
        cp16(d + SPLIT_BYTES + c * 16,     &g_zh[1][aoff + c * 8]);
        cp16(d + 2 * SPLIT_BYTES + c * 16, &g_ch[0][boff + c * 8]);
        cp16(d + 3 * SPLIT_BYTES + c * 16, &g_ch[1][boff + c * 8]);
    }
}

// ---------------------------------------------------------------------------
// Kernel 2: HMMA fp16 3-term exact-split GEMM + bias + argmin
// 128 threads (4 warps), warp tile 64x64, block 128x128, k32 stages,
// 2-deep cp.async ring (issue after barrier), ldmatrix A+B fragments.
// Terms: a0b0 + a0b1 + a1b0 (a1b1 dropped: <= 2^-22 rel, << argmin gap)
// ---------------------------------------------------------------------------
__global__ __launch_bounds__(128, 2) void vq_hmma_kernel(const float* __restrict__ adj)
{
    extern __shared__ __align__(16) char smem[];
    unsigned long long* sRed = reinterpret_cast<unsigned long long*>(smem + SRED_OFF);
    const uint32_t sbase = smem_u32(smem);

    const int tid    = threadIdx.x;
    const int lane   = tid & 31;
    const int wid    = tid >> 5;
    const int warp_m = wid & 1;       // 0..1  (64 rows)
    const int warp_n = wid >> 1;      // 0..1  (64 cols)
    const int m0     = blockIdx.x * BLK_M;

#pragma unroll
    for (int i = 0; i < 8; i++) sRed[tid + 128 * i] = ~0ULL;

    int prev8[8];
#pragma unroll
    for (int mi = 0; mi < 4; mi++)
#pragma unroll
        for (int h = 0; h < 2; h++)
            prev8[mi * 2 + h] = g_prev[m0 + warp_m * 64 + mi * 16 + (lane >> 2) + h * 8];

    float acc[4][8][4];
#pragma unroll
    for (int mi = 0; mi < 4; mi++)
#pragma unroll
        for (int ni = 0; ni < 8; ni++)
#pragma unroll
            for (int e = 0; e < 4; e++) acc[mi][ni][e] = 0.f;

    // fragment addressing
    const int arow8 = ((lane >> 3) & 1) * 8 + (lane & 7);  // A row-in-16
    const int akoff = (lane >> 4) * 16;                    // A k-half byte off
    const int bq = lane >> 3, br = lane & 7;               // B matrix q, row
    const int boffs = ((bq >> 1) * 8 + br) * ROW_BYTES + (bq & 1) * 16;

    // prologue: stage 0 into buf 0
    stage_cp(sbase, 0, m0, 0, tid);
    CP_COMMIT();

    for (int s = 0; s < NSTAGES; s++) {
        CP_WAIT0();
        __syncthreads();                     // stage s visible, prior compute done
        if (s + 1 < NSTAGES) {               // overlap next load with compute
            stage_cp(sbase, (s + 1) & 1, m0, s + 1, tid);
            CP_COMMIT();
        }

        const uint32_t buf = sbase + (s & 1) * STAGE_BYTES;
        const uint32_t aB0 = buf + (warp_m * 64 + arow8) * ROW_BYTES + akoff;
        const uint32_t bB0 = buf + 2 * SPLIT_BYTES + warp_n * 64 * ROW_BYTES + boffs;

#pragma unroll
        for (int ks = 0; ks < 2; ks++) {
            const uint32_t kso = ks * 32;
            // B fragments: [split][ni 0..7][2]
            uint32_t bF[2][8][2];
#pragma unroll
            for (int sp = 0; sp < 2; sp++)
#pragma unroll
                for (int pr = 0; pr < 4; pr++) {
                    uint32_t r[4];
                    ldmatrix_x4(r, bB0 + sp * SPLIT_BYTES + pr * 16 * ROW_BYTES + kso);
                    bF[sp][pr * 2 + 0][0] = r[0]; bF[sp][pr * 2 + 0][1] = r[1];
                    bF[sp][pr * 2 + 1][0] = r[2]; bF[sp][pr * 2 + 1][1] = r[3];
                }
            // A split 0: a0b0 + a0b1
            {
                uint32_t aF[4][4];
#pragma unroll
                for (int mi = 0; mi < 4; mi++)
                    ldmatrix_x4(aF[mi], aB0 + mi * 16 * ROW_BYTES + kso);
#pragma unroll
                for (int mi = 0; mi < 4; mi++)
#pragma unroll
                    for (int ni = 0; ni < 8; ni++) {
                        mma_f16(acc[mi][ni], aF[mi], bF[0][ni]);
                        mma_f16(acc[mi][ni], aF[mi], bF[1][ni]);
                    }
            }
            // A split 1: a1b0
            {
                uint32_t aF[4][4];
#pragma unroll
                for (int mi = 0; mi < 4; mi++)
                    ldmatrix_x4(aF[mi], aB0 + SPLIT_BYTES + mi * 16 * ROW_BYTES + kso);
#pragma unroll
                for (int mi = 0; mi < 4; mi++)
#pragma unroll
                    for (int ni = 0; ni < 8; ni++)
                        mma_f16(acc[mi][ni], aF[mi], bF[0][ni]);
            }
        }

        // epilogue at end of each n-tile (every 16 stages)
        if ((s & 15) == 15) {
            const int n0 = (s >> 4) * BLK_N;
#pragma unroll
            for (int mi = 0; mi < 4; mi++) {
#pragma unroll
                for (int h = 0; h < 2; h++) {
                    const int r = warp_m * 64 + mi * 16 + (lane >> 2) + h * 8;
                    const float* arow = adj + (size_t)prev8[mi * 2 + h] * KCB;
                    unsigned long long b = ~0ULL;
#pragma unroll
                    for (int ni = 0; ni < 8; ni++) {
                        const int n = n0 + warp_n * 64 + ni * 8 + (lane & 3) * 2;
                        float2 g  = *reinterpret_cast<const float2*>(arow + n);
                        float2 cn = *reinterpret_cast<const float2*>(g_cnorm + n);
                        float s0 = cn.x - 2.0f * acc[mi][ni][h * 2 + 0] - sig08(g.x);
                        float s1 = cn.y - 2.0f * acc[mi][ni][h * 2 + 1] - sig08(g.y);
                        unsigned u0 = __float_as_uint(s0);
                        u0 = (u0 & 0x80000000u) ? ~u0 : (u0 | 0x80000000u);
                        unsigned u1 = __float_as_uint(s1);
                        u1 = (u1 & 0x80000000u) ? ~u1 : (u1 | 0x80000000u);
                        unsigned long long c0 = ((unsigned long long)u0 << 32) | (unsigned)n;
                        unsigned long long c1 = ((unsigned long long)u1 << 32) | (unsigned)(n + 1);
                        b = (c0 < b) ? c0 : b;
                        b = (c1 < b) ? c1 : b;
                    }
                    unsigned long long* slot = &sRed[r * 8 + warp_n * 4 + (lane & 3)];
                    if (b < *slot) *slot = b;   // single-owner slot
                }
            }
#pragma unroll
            for (int mi = 0; mi < 4; mi++)
#pragma unroll
                for (int ni = 0; ni < 8; ni++)
#pragma unroll
                    for (int e = 0; e < 4; e++) acc[mi][ni][e] = 0.f;
        }
    }

    __syncthreads();
    {
        unsigned long long b = sRed[tid * 8];
#pragma unroll
        for (int t = 1; t < 8; t++) {
            unsigned long long c = sRed[tid * 8 + t];
            b = (c < b) ? c : b;
        }
        g_idx[m0 + tid] = (int)(b & 0xffffffffu);
    }
}

// ---------------------------------------------------------------------------
// Kernel 3: gather z_q = codebook[idx], write outputs, per-row squared error
// ---------------------------------------------------------------------------
__global__ void gather_kernel(const float* __restrict__ zr,
                              const float* __restrict__ zi,
                              const float* __restrict__ cb,
                              float* __restrict__ out)
{
    __shared__ float sw[4];
    const int row = blockIdx.x;
    const int tid = threadIdx.x;
    const int idx = g_idx[row];
    const int j   = tid * 4;

    float4 c = *reinterpret_cast<const float4*>(cb + (size_t)idx * D2 + j);
    float4 z;
    float* o;
    if (j < DHALF) {
        z = *reinterpret_cast<const float4*>(zr + (size_t)row * DHALF + j);
        o = out + OUT_REAL_OFF + (size_t)row * DHALF + j;
    } else {
        z = *reinterpret_cast<const float4*>(zi + (size_t)row * DHALF + (j - DHALF));
        o = out + OUT_IMAG_OFF + (size_t)row * DHALF + (j - DHALF);
    }
    *reinterpret_cast<float4*>(o) = c;

    float dx = c.x - z.x, dy = c.y - z.y, dz = c.z - z.z, dw = c.w - z.w;
    float s = dx * dx + dy * dy + dz * dz + dw * dw;
#pragma unroll
    for (int of = 16; of; of >>= 1) s += __shfl_xor_sync(0xffffffffu, s, of);
    if ((tid & 31) == 0) sw[tid >> 5] = s;
    __syncthreads();
    if (tid == 0) {
        g_rowsum[row] = sw[0] + sw[1] + sw[2] + sw[3];
        out[OUT_IDX_OFF + row] = (float)idx;
    }
}

// ---------------------------------------------------------------------------
// Kernel 4: deterministic final loss reduction
// ---------------------------------------------------------------------------
__global__ void loss_kernel(float* __restrict__ out) {
    __shared__ float sm[1024];
    const int tid = threadIdx.x;
    float s = 0.f;
#pragma unroll 1
    for (int k = 0; k < 32; k++) s += g_rowsum[tid + 1024 * k];
    sm[tid] = s;
    __syncthreads();
    for (int off = 512; off; off >>= 1) {
        if (tid < off) sm[tid] += sm[tid + off];
        __syncthreads();
    }
    if (tid == 0) out[OUT_LOSS_OFF] = sm[0] * (1.01f / 16777216.0f);
}

// ---------------------------------------------------------------------------
extern "C" void kernel_launch(void* const* d_in, const int* in_sizes, int n_in,
                              void* d_out, int out_size) {
    const float* zr   = (const float*)d_in[0];
    const float* zi   = (const float*)d_in[1];
    const void*  prev = d_in[2];
    const float* cb   = (const float*)d_in[3];
    const float* adj  = (const float*)d_in[4];
    float* out = (float*)d_out;

    cudaFuncSetAttribute(vq_hmma_kernel,
                         cudaFuncAttributeMaxDynamicSharedMemorySize, SMEM_TOTAL);

    prev_kernel<<<(M_TOTAL + 255) / 256, 256>>>(prev);
    cnorm_kernel<<<KCB / 8, 256>>>(cb);
    split_z_kernel<<<(M_TOTAL * D2 / 4) / 256, 256>>>(zr, zi);
    split_cb_kernel<<<(KCB * D2 / 4) / 256, 256>>>(cb);
    vq_hmma_kernel<<<M_TOTAL / BLK_M, 128, SMEM_TOTAL>>>(adj);
    gather_kernel<<<M_TOTAL, 128>>>(zr, zi, cb, out);
    loss_kernel<<<1, 1024>>>(out);
}

// round 10
// speedup vs baseline: 1.0334x; 1.0334x over previous
#include <cuda_runtime.h>
#include <cuda_fp16.h>
#include <cstdint>

#define M_TOTAL 32768
#define DHALF   256
#define D2      512
#define KCB     4096

#define BLK_M 128
#define BLK_N 128
#define NTILES  (KCB / BLK_N)       // 32
#define KSTAGES (D2 / 32)           // 16 k32-stages per n-tile
#define NSTAGES (NTILES * KSTAGES)  // 512

// smem: per split tile 128 rows x 80B (32 fp16 = 64B data + 16B pad)
#define ROW_BYTES   80
#define SPLIT_BYTES (128 * ROW_BYTES)            // 10240
#define STAGE_BYTES (4 * SPLIT_BYTES)            // A0,A1,B0,B1 = 40960
#define SRED_OFF    (2 * STAGE_BYTES)            // 81920 (2-deep ring)
#define SMEM_TOTAL  (SRED_OFF + BLK_M * 16 * 8)  // + 16KB keys = 98304

#define OUT_REAL_OFF 0
#define OUT_IMAG_OFF 8388608
#define OUT_LOSS_OFF 16777216
#define OUT_IDX_OFF  16777217

__device__ __align__(16) float g_cnorm[KCB];
__device__ int   g_prev[M_TOTAL];
__device__ int   g_idx[M_TOTAL];
__device__ float g_rowsum[M_TOTAL];
// 2-way fp16 splits, K-major [row][k 0..511]
__device__ __align__(16) __half g_zh[2][(size_t)M_TOTAL * D2];
__device__ __align__(16) __half g_ch[2][(size_t)KCB * D2];

// ---------------------------------------------------------------------------
__device__ __forceinline__ uint32_t smem_u32(const void* p) {
    uint32_t a;
    asm("{ .reg .u64 t; cvta.to.shared.u64 t, %1; cvt.u32.u64 %0, t; }"
        : "=r"(a) : "l"(p));
    return a;
}

__device__ __forceinline__ void cp16(uint32_t dst, const void* src) {
    asm volatile("cp.async.cg.shared.global [%0], [%1], 16;"
                 :: "r"(dst), "l"(src) : "memory");
}
#define CP_COMMIT() asm volatile("cp.async.commit_group;" ::: "memory")
#define CP_WAIT0()  asm volatile("cp.async.wait_group 0;" ::: "memory")

__device__ __forceinline__ void ldmatrix_x4(uint32_t* r, uint32_t addr) {
    asm volatile("ldmatrix.sync.aligned.m8n8.x4.shared.b16 {%0,%1,%2,%3}, [%4];"
                 : "=r"(r[0]), "=r"(r[1]), "=r"(r[2]), "=r"(r[3]) : "r"(addr));
}

__device__ __forceinline__ void mma_f16(float* d, const uint32_t* a,
                                        const uint32_t* b) {
    asm volatile(
        "mma.sync.aligned.m16n8k16.row.col.f32.f16.f16.f32 "
        "{%0,%1,%2,%3},{%4,%5,%6,%7},{%8,%9},{%0,%1,%2,%3};"
        : "+f"(d[0]), "+f"(d[1]), "+f"(d[2]), "+f"(d[3])
        : "r"(a[0]), "r"(a[1]), "r"(a[2]), "r"(a[3]), "r"(b[0]), "r"(b[1]));
}

// exact 2-way fp16 split: v = h0 + h1 (to ~2^-22 rel)
__device__ __forceinline__ void split2(float v, unsigned short& s0,
                                       unsigned short& s1) {
    __half h0 = __float2half_rn(v);
    __half h1 = __float2half_rn(v - __half2float(h0));
    s0 = __half_as_ushort(h0);
    s1 = __half_as_ushort(h1);
}

__device__ __forceinline__ float sig08(float x) {
    float x2 = x * x;
    // 0.8*sigmoid(x) = 0.4 + 0.8*x*p(x^2), odd Taylor to x^9 (|x| <= 1)
    float p = 2.1356922e-05f;
    p = fmaf(p, x2, -2.1081349e-04f);
    p = fmaf(p, x2,  2.0833334e-03f);
    p = fmaf(p, x2, -2.0833333e-02f);
    p = fmaf(p, x2,  0.25f);
    float s = fmaf(0.8f * x, p, 0.4f);
    if (fabsf(x) > 1.0f) s = 0.8f / (1.0f + __expf(-x));
    return s;
}

// ---------------------------------------------------------------------------
// Kernel 0: normalize prev_symbol_idx (int64 vs int32 sniff)
// ---------------------------------------------------------------------------
__global__ void prev_kernel(const void* __restrict__ p) {
    const long long* p64 = (const long long*)p;
    const int*       p32 = (const int*)p;
    bool is64 = true;
    for (int t = 0; t < 64; t++) {
        long long v = p64[t];
        if (v < 0 || v >= KCB) { is64 = false; break; }
    }
    int i = blockIdx.x * blockDim.x + threadIdx.x;
    if (i < M_TOTAL) g_prev[i] = is64 ? (int)p64[i] : p32[i];
}

// ---------------------------------------------------------------------------
// Kernel 1: cnorm[k] = ||codebook[k]||^2 (exact, f32)
// ---------------------------------------------------------------------------
__global__ void cnorm_kernel(const float* __restrict__ cb) {
    int warp = (blockIdx.x * blockDim.x + threadIdx.x) >> 5;
    int lane = threadIdx.x & 31;
    if (warp >= KCB) return;
    const float4* row = reinterpret_cast<const float4*>(cb + (size_t)warp * D2);
    float s = 0.f;
#pragma unroll
    for (int w = 0; w < 4; w++) {
        float4 v = row[lane + 32 * w];
        s += v.x * v.x + v.y * v.y + v.z * v.z + v.w * v.w;
    }
#pragma unroll
    for (int o = 16; o; o >>= 1) s += __shfl_xor_sync(0xffffffffu, s, o);
    if (lane == 0) g_cnorm[warp] = s;
}

// ---------------------------------------------------------------------------
// Split kernels: f32 -> 2x fp16 slices
// ---------------------------------------------------------------------------
__global__ void split_z_kernel(const float* __restrict__ zr,
                               const float* __restrict__ zi) {
    int g = blockIdx.x * blockDim.x + threadIdx.x;
    int m  = g >> 7;
    int k4 = (g & 127) * 4;
    float4 v = (k4 < DHALF)
        ? *reinterpret_cast<const float4*>(zr + (size_t)m * DHALF + k4)
        : *reinterpret_cast<const float4*>(zi + (size_t)m * DHALF + (k4 - DHALF));
    ushort4 o0, o1;
    split2(v.x, o0.x, o1.x);
    split2(v.y, o0.y, o1.y);
    split2(v.z, o0.z, o1.z);
    split2(v.w, o0.w, o1.w);
    size_t off = (size_t)m * D2 + k4;
    *reinterpret_cast<ushort4*>(&g_zh[0][off]) = o0;
    *reinterpret_cast<ushort4*>(&g_zh[1][off]) = o1;
}

__global__ void split_cb_kernel(const float* __restrict__ cb) {
    int g = blockIdx.x * blockDim.x + threadIdx.x;
    size_t off = (size_t)g * 4;
    float4 v = *reinterpret_cast<const float4*>(cb + off);
    ushort4 o0, o1;
    split2(v.x, o0.x, o1.x);
    split2(v.y, o0.y, o1.y);
    split2(v.z, o0.z, o1.z);
    split2(v.w, o0.w, o1.w);
    *reinterpret_cast<ushort4*>(&g_ch[0][off]) = o0;
    *reinterpret_cast<ushort4*>(&g_ch[1][off]) = o1;
}

// ---------------------------------------------------------------------------
// cp.async one k32-stage: 4 tiles x 128 rows x 64B; 256 threads,
// thread covers (row = tid&127, 32B half = tid>>7) -> 8 cp16 per thread
// ---------------------------------------------------------------------------
__device__ __forceinline__ void stage_cp(uint32_t sbase, int buf, int m0,
                                         int s, int tid) {
    const int nt  = s >> 4;
    const int kb  = (s & 15) * 32;
    const int row = tid & 127;
    const int hf  = tid >> 7;                   // 0 or 1 (32B halves)
    const uint32_t d = sbase + buf * STAGE_BYTES + row * ROW_BYTES + hf * 32;
    const size_t aoff = (size_t)(m0 + row) * D2 + kb + hf * 16;
    const size_t boff = (size_t)(nt * BLK_N + row) * D2 + kb + hf * 16;
#pragma unroll
    for (int c = 0; c < 2; c++) {
        cp16(d + c * 16,                   &g_zh[0][aoff + c * 8]);
        cp16(d + SPLIT_BYTES + c * 16,     &g_zh[1][aoff + c * 8]);
        cp16(d + 2 * SPLIT_BYTES + c * 16, &g_ch[0][boff + c * 8]);
        cp16(d + 3 * SPLIT_BYTES + c * 16, &g_ch[1][boff + c * 8]);
    }
}

// ---------------------------------------------------------------------------
// Kernel 2: HMMA fp16 3-term exact-split GEMM + bias + argmin
// 256 threads (8 warps), warps 2(m) x 4(n), warp tile 64x32, block 128x128,
// k32 stages (two k16 substeps), 2-deep cp.async ring, ldmatrix A+B frags.
// Terms: a0b0 + a0b1 + a1b0 (a1b1 dropped: <= 2^-22 rel, << argmin gap)
// ---------------------------------------------------------------------------
__global__ __launch_bounds__(256, 2) void vq_hmma_kernel(const float* __restrict__ adj)
{
    extern __shared__ __align__(16) char smem[];
    unsigned long long* sRed = reinterpret_cast<unsigned long long*>(smem + SRED_OFF);
    const uint32_t sbase = smem_u32(smem);

    const int tid    = threadIdx.x;
    const int lane   = tid & 31;
    const int wid    = tid >> 5;
    const int warp_m = wid & 1;       // 0..1  (64 rows)
    const int warp_n = wid >> 1;      // 0..3  (32 cols)
    const int m0     = blockIdx.x * BLK_M;

#pragma unroll
    for (int i = 0; i < 8; i++) sRed[tid + 256 * i] = ~0ULL;

    int prev8[8];
#pragma unroll
    for (int mi = 0; mi < 4; mi++)
#pragma unroll
        for (int h = 0; h < 2; h++)
            prev8[mi * 2 + h] = g_prev[m0 + warp_m * 64 + mi * 16 + (lane >> 2) + h * 8];

    float acc[4][4][4];
#pragma unroll
    for (int mi = 0; mi < 4; mi++)
#pragma unroll
        for (int ni = 0; ni < 4; ni++)
#pragma unroll
            for (int e = 0; e < 4; e++) acc[mi][ni][e] = 0.f;

    // fragment addressing
    const int arow8 = ((lane >> 3) & 1) * 8 + (lane & 7);    // A row-in-16
    const int akoff = (lane >> 4) * 16;                      // A k-half byte off
    const int bq = lane >> 3, br = lane & 7;                 // B matrix q, row
    const int boffs = ((bq >> 1) * 8 + br) * ROW_BYTES + (bq & 1) * 16;

    // prologue: stage 0 into buf 0
    stage_cp(sbase, 0, m0, 0, tid);
    CP_COMMIT();

    for (int s = 0; s < NSTAGES; s++) {
        CP_WAIT0();
        __syncthreads();                     // stage s visible, prior compute done
        if (s + 1 < NSTAGES) {               // overlap next load with compute
            stage_cp(sbase, (s + 1) & 1, m0, s + 1, tid);
            CP_COMMIT();
        }

        const uint32_t buf = sbase + (s & 1) * STAGE_BYTES;
        const uint32_t aB0 = buf + (warp_m * 64 + arow8) * ROW_BYTES + akoff;
        const uint32_t bB0 = buf + 2 * SPLIT_BYTES + (warp_n * 32) * ROW_BYTES + boffs;

#pragma unroll
        for (int ks = 0; ks < 2; ks++) {
            const uint32_t kso = ks * 32;
            // B fragments via ldmatrix.x4: [split][ni][2]
            uint32_t bF[2][4][2];
#pragma unroll
            for (int sp = 0; sp < 2; sp++) {
                const uint32_t bb = bB0 + sp * SPLIT_BYTES + kso;
                uint32_t r0[4], r1[4];
                ldmatrix_x4(r0, bb);                   // ni 0,1
                ldmatrix_x4(r1, bb + 16 * ROW_BYTES);  // ni 2,3
                bF[sp][0][0] = r0[0]; bF[sp][0][1] = r0[1];
                bF[sp][1][0] = r0[2]; bF[sp][1][1] = r0[3];
                bF[sp][2][0] = r1[0]; bF[sp][2][1] = r1[1];
                bF[sp][3][0] = r1[2]; bF[sp][3][1] = r1[3];
            }
            // A split 0: terms a0b0 + a0b1
            {
                uint32_t aF[4][4];
#pragma unroll
                for (int mi = 0; mi < 4; mi++)
                    ldmatrix_x4(aF[mi], aB0 + mi * 16 * ROW_BYTES + kso);
#pragma unroll
                for (int mi = 0; mi < 4; mi++)
#pragma unroll
                    for (int ni = 0; ni < 4; ni++) {
                        mma_f16(acc[mi][ni], aF[mi], bF[0][ni]);
                        mma_f16(acc[mi][ni], aF[mi], bF[1][ni]);
                    }
            }
            // A split 1: term a1b0 only
            {
                uint32_t aF[4][4];
#pragma unroll
                for (int mi = 0; mi < 4; mi++)
                    ldmatrix_x4(aF[mi], aB0 + SPLIT_BYTES + mi * 16 * ROW_BYTES + kso);
#pragma unroll
                for (int mi = 0; mi < 4; mi++)
#pragma unroll
                    for (int ni = 0; ni < 4; ni++)
                        mma_f16(acc[mi][ni], aF[mi], bF[0][ni]);
            }
        }

        // epilogue at end of each n-tile (every 16 k32-stages)
        if ((s & 15) == 15) {
            const int n0 = (s >> 4) * BLK_N;
#pragma unroll
            for (int mi = 0; mi < 4; mi++) {
#pragma unroll
                for (int h = 0; h < 2; h++) {
                    const int r = warp_m * 64 + mi * 16 + (lane >> 2) + h * 8;
                    const float* arow = adj + (size_t)prev8[mi * 2 + h] * KCB;
                    unsigned long long b = ~0ULL;
#pragma unroll
                    for (int ni = 0; ni < 4; ni++) {
                        const int n = n0 + warp_n * 32 + ni * 8 + (lane & 3) * 2;
                        float2 g  = *reinterpret_cast<const float2*>(arow + n);
                        float2 cn = *reinterpret_cast<const float2*>(g_cnorm + n);
                        float s0 = cn.x - 2.0f * acc[mi][ni][h * 2 + 0] - sig08(g.x);
                        float s1 = cn.y - 2.0f * acc[mi][ni][h * 2 + 1] - sig08(g.y);
                        unsigned u0 = __float_as_uint(s0);
                        u0 = (u0 & 0x80000000u) ? ~u0 : (u0 | 0x80000000u);
                        unsigned u1 = __float_as_uint(s1);
                        u1 = (u1 & 0x80000000u) ? ~u1 : (u1 | 0x80000000u);
                        unsigned long long c0 = ((unsigned long long)u0 << 32) | (unsigned)n;
                        unsigned long long c1 = ((unsigned long long)u1 << 32) | (unsigned)(n + 1);
                        b = (c0 < b) ? c0 : b;
                        b = (c1 < b) ? c1 : b;
                    }
                    unsigned long long* slot = &sRed[r * 16 + warp_n * 4 + (lane & 3)];
                    if (b < *slot) *slot = b;   // single-owner slot
                }
            }
#pragma unroll
            for (int mi = 0; mi < 4; mi++)
#pragma unroll
                for (int ni = 0; ni < 4; ni++)
#pragma unroll
                    for (int e = 0; e < 4; e++) acc[mi][ni][e] = 0.f;
        }
    }

    __syncthreads();
    if (tid < BLK_M) {
        unsigned long long b = sRed[tid * 16];
#pragma unroll
        for (int t = 1; t < 16; t++) {
            unsigned long long c = sRed[tid * 16 + t];
            b = (c < b) ? c : b;
        }
        g_idx[m0 + tid] = (int)(b & 0xffffffffu);
    }
}

// ---------------------------------------------------------------------------
// Kernel 3: gather z_q = codebook[idx], write outputs, per-row squared error
// ---------------------------------------------------------------------------
__global__ void gather_kernel(const float* __restrict__ zr,
                              const float* __restrict__ zi,
                              const float* __restrict__ cb,
                              float* __restrict__ out)
{
    __shared__ float sw[4];
    const int row = blockIdx.x;
    const int tid = threadIdx.x;
    const int idx = g_idx[row];
    const int j   = tid * 4;

    float4 c = *reinterpret_cast<const float4*>(cb + (size_t)idx * D2 + j);
    float4 z;
    float* o;
    if (j < DHALF) {
        z = *reinterpret_cast<const float4*>(zr + (size_t)row * DHALF + j);
        o = out + OUT_REAL_OFF + (size_t)row * DHALF + j;
    } else {
        z = *reinterpret_cast<const float4*>(zi + (size_t)row * DHALF + (j - DHALF));
        o = out + OUT_IMAG_OFF + (size_t)row * DHALF + (j - DHALF);
    }
    *reinterpret_cast<float4*>(o) = c;

    float dx = c.x - z.x, dy = c.y - z.y, dz = c.z - z.z, dw = c.w - z.w;
    float s = dx * dx + dy * dy + dz * dz + dw * dw;
#pragma unroll
    for (int of = 16; of; of >>= 1) s += __shfl_xor_sync(0xffffffffu, s, of);
    if ((tid & 31) == 0) sw[tid >> 5] = s;
    __syncthreads();
    if (tid == 0) {
        g_rowsum[row] = sw[0] + sw[1] + sw[2] + sw[3];
        out[OUT_IDX_OFF + row] = (float)idx;
    }
}

// ---------------------------------------------------------------------------
// Kernel 4: deterministic final loss reduction
// ---------------------------------------------------------------------------
__global__ void loss_kernel(float* __restrict__ out) {
    __shared__ float sm[1024];
    const int tid = threadIdx.x;
    float s = 0.f;
#pragma unroll 1
    for (int k = 0; k < 32; k++) s += g_rowsum[tid + 1024 * k];
    sm[tid] = s;
    __syncthreads();
    for (int off = 512; off; off >>= 1) {
        if (tid < off) sm[tid] += sm[tid + off];
        __syncthreads();
    }
    if (tid == 0) out[OUT_LOSS_OFF] = sm[0] * (1.01f / 16777216.0f);
}

// ---------------------------------------------------------------------------
extern "C" void kernel_launch(void* const* d_in, const int* in_sizes, int n_in,
                              void* d_out, int out_size) {
    const float* zr   = (const float*)d_in[0];
    const float* zi   = (const float*)d_in[1];
    const void*  prev = d_in[2];
    const float* cb   = (const float*)d_in[3];
    const float* adj  = (const float*)d_in[4];
    float* out = (float*)d_out;

    cudaFuncSetAttribute(vq_hmma_kernel,
                         cudaFuncAttributeMaxDynamicSharedMemorySize, SMEM_TOTAL);

    prev_kernel<<<(M_TOTAL + 255) / 256, 256>>>(prev);
    cnorm_kernel<<<KCB / 8, 256>>>(cb);
    split_z_kernel<<<(M_TOTAL * D2 / 4) / 256, 256>>>(zr, zi);
    split_cb_kernel<<<(KCB * D2 / 4) / 256, 256>>>(cb);
    vq_hmma_kernel<<<M_TOTAL / BLK_M, 256, SMEM_TOTAL>>>(adj);
    gather_kernel<<<M_TOTAL, 128>>>(zr, zi, cb, out);
    loss_kernel<<<1, 1024>>>(out);
}

// round 11
// speedup vs baseline: 1.2492x; 1.2088x over previous
#include <cuda_runtime.h>
#include <cuda_fp16.h>
#include <cstdint>

#define M_TOTAL 32768
#define DHALF   256
#define D2      512
#define KCB     4096

#define BLK_M 128
#define BLK_N 128
#define NTILES  (KCB / BLK_N)       // 32
#define KSTAGES (D2 / 16)           // 32 k16-stages per n-tile
#define NSTAGES (NTILES * KSTAGES)  // 1024

// smem: per split tile 128 rows x 48B (16 fp16 = 32B data + 16B pad)
#define SPLIT_BYTES 6144
#define STAGE_BYTES (4 * SPLIT_BYTES)            // A0,A1,B0,B1 = 24576
#define SRED_OFF    (3 * STAGE_BYTES)            // 73728 (3-deep ring)
#define SMEM_TOTAL  (SRED_OFF + BLK_M * 16 * 8)  // + 16KB keys = 90112

#define OUT_REAL_OFF 0
#define OUT_IMAG_OFF 8388608
#define OUT_LOSS_OFF 16777216
#define OUT_IDX_OFF  16777217

__device__ __align__(16) float g_cnorm[KCB];
__device__ int   g_prev[M_TOTAL];
__device__ int   g_idx[M_TOTAL];
__device__ float g_rowsum[M_TOTAL];
// 2-way fp16 splits, K-major [row][k 0..511]
__device__ __align__(16) __half g_zh[2][(size_t)M_TOTAL * D2];
__device__ __align__(16) __half g_ch[2][(size_t)KCB * D2];

// ---------------------------------------------------------------------------
__device__ __forceinline__ uint32_t smem_u32(const void* p) {
    uint32_t a;
    asm("{ .reg .u64 t; cvta.to.shared.u64 t, %1; cvt.u32.u64 %0, t; }"
        : "=r"(a) : "l"(p));
    return a;
}

__device__ __forceinline__ void cp16(uint32_t dst, const void* src) {
    asm volatile("cp.async.cg.shared.global [%0], [%1], 16;"
                 :: "r"(dst), "l"(src) : "memory");
}
#define CP_COMMIT() asm volatile("cp.async.commit_group;" ::: "memory")
#define CP_WAIT1()  asm volatile("cp.async.wait_group 1;" ::: "memory")

__device__ __forceinline__ void ldmatrix_x4(uint32_t* r, uint32_t addr) {
    asm volatile("ldmatrix.sync.aligned.m8n8.x4.shared.b16 {%0,%1,%2,%3}, [%4];"
                 : "=r"(r[0]), "=r"(r[1]), "=r"(r[2]), "=r"(r[3]) : "r"(addr));
}

__device__ __forceinline__ void mma_f16(float* d, const uint32_t* a,
                                        const uint32_t* b) {
    asm volatile(
        "mma.sync.aligned.m16n8k16.row.col.f32.f16.f16.f32 "
        "{%0,%1,%2,%3},{%4,%5,%6,%7},{%8,%9},{%0,%1,%2,%3};"
        : "+f"(d[0]), "+f"(d[1]), "+f"(d[2]), "+f"(d[3])
        : "r"(a[0]), "r"(a[1]), "r"(a[2]), "r"(a[3]), "r"(b[0]), "r"(b[1]));
}

// exact 2-way fp16 split: v = h0 + h1 (to ~2^-22 rel)
__device__ __forceinline__ void split2(float v, unsigned short& s0,
                                       unsigned short& s1) {
    __half h0 = __float2half_rn(v);
    __half h1 = __float2half_rn(v - __half2float(h0));
    s0 = __half_as_ushort(h0);
    s1 = __half_as_ushort(h1);
}

__device__ __forceinline__ float sig08(float x) {
    float x2 = x * x;
    // 0.8*sigmoid(x) = 0.4 + 0.8*x*p(x^2), odd Taylor to x^9 (|x| <= 1)
    float p = 2.1356922e-05f;
    p = fmaf(p, x2, -2.1081349e-04f);
    p = fmaf(p, x2,  2.0833334e-03f);
    p = fmaf(p, x2, -2.0833333e-02f);
    p = fmaf(p, x2,  0.25f);
    float s = fmaf(0.8f * x, p, 0.4f);
    if (fabsf(x) > 1.0f) s = 0.8f / (1.0f + __expf(-x));
    return s;
}

// ---------------------------------------------------------------------------
// Kernel 0: normalize prev_symbol_idx (int64 vs int32 sniff)
// ---------------------------------------------------------------------------
__global__ void prev_kernel(const void* __restrict__ p) {
    const long long* p64 = (const long long*)p;
    const int*       p32 = (const int*)p;
    bool is64 = true;
    for (int t = 0; t < 64; t++) {
        long long v = p64[t];
        if (v < 0 || v >= KCB) { is64 = false; break; }
    }
    int i = blockIdx.x * blockDim.x + threadIdx.x;
    if (i < M_TOTAL) g_prev[i] = is64 ? (int)p64[i] : p32[i];
}

// ---------------------------------------------------------------------------
// Kernel 1: cnorm[k] = ||codebook[k]||^2 (exact, f32)
// ---------------------------------------------------------------------------
__global__ void cnorm_kernel(const float* __restrict__ cb) {
    int warp = (blockIdx.x * blockDim.x + threadIdx.x) >> 5;
    int lane = threadIdx.x & 31;
    if (warp >= KCB) return;
    const float4* row = reinterpret_cast<const float4*>(cb + (size_t)warp * D2);
    float s = 0.f;
#pragma unroll
    for (int w = 0; w < 4; w++) {
        float4 v = row[lane + 32 * w];
        s += v.x * v.x + v.y * v.y + v.z * v.z + v.w * v.w;
    }
#pragma unroll
    for (int o = 16; o; o >>= 1) s += __shfl_xor_sync(0xffffffffu, s, o);
    if (lane == 0) g_cnorm[warp] = s;
}

// ---------------------------------------------------------------------------
// Kernel 2 (merged): f32 -> 2x fp16 slices for both z and codebook.
// Blocks [0, 16384) handle z, blocks [16384, 18432) handle codebook.
// ---------------------------------------------------------------------------
__global__ void split_kernel(const float* __restrict__ zr,
                             const float* __restrict__ zi,
                             const float* __restrict__ cb) {
    const int zblocks = (M_TOTAL * D2 / 4) / 256;   // 16384
    float4 v;
    __half* d0;
    __half* d1;
    if (blockIdx.x < zblocks) {
        int g  = blockIdx.x * 256 + threadIdx.x;
        int m  = g >> 7;
        int k4 = (g & 127) * 4;
        v = (k4 < DHALF)
            ? *reinterpret_cast<const float4*>(zr + (size_t)m * DHALF + k4)
            : *reinterpret_cast<const float4*>(zi + (size_t)m * DHALF + (k4 - DHALF));
        size_t off = (size_t)m * D2 + k4;
        d0 = &g_zh[0][off]; d1 = &g_zh[1][off];
    } else {
        int g = (blockIdx.x - zblocks) * 256 + threadIdx.x;
        size_t off = (size_t)g * 4;
        v = *reinterpret_cast<const float4*>(cb + off);
        d0 = &g_ch[0][off]; d1 = &g_ch[1][off];
    }
    ushort4 o0, o1;
    split2(v.x, o0.x, o1.x);
    split2(v.y, o0.y, o1.y);
    split2(v.z, o0.z, o1.z);
    split2(v.w, o0.w, o1.w);
    *reinterpret_cast<ushort4*>(d0) = o0;
    *reinterpret_cast<ushort4*>(d1) = o1;
}

// ---------------------------------------------------------------------------
// cp.async one k16-stage (4 tiles x 128 rows x 32B); 4 x 16B per thread
// ---------------------------------------------------------------------------
__device__ __forceinline__ void stage_cp(uint32_t sbase, int buf, int m0,
                                         int s, int tid) {
    const int nt = s >> 5;
    const int kb = (s & 31) * 16;
    const int row = tid >> 1, h = tid & 1;
    const uint32_t d = sbase + buf * STAGE_BYTES + row * 48 + h * 16;
    const size_t aoff = (size_t)(m0 + row) * D2 + kb + h * 8;
    const size_t boff = (size_t)(nt * BLK_N + row) * D2 + kb + h * 8;
    cp16(d,                   &g_zh[0][aoff]);
    cp16(d + SPLIT_BYTES,     &g_zh[1][aoff]);
    cp16(d + 2 * SPLIT_BYTES, &g_ch[0][boff]);
    cp16(d + 3 * SPLIT_BYTES, &g_ch[1][boff]);
}

// ---------------------------------------------------------------------------
// Kernel 3: HMMA fp16 3-term exact-split GEMM + bias + argmin
// Block 128x128, warps 2(m) x 4(n), warp tile 64x32, k16 stages,
// 3-deep cp.async ring (wait_group 1), ldmatrix for A and B fragments.
// Terms: a0b0 + a0b1 + a1b0 (a1b1 dropped: <= 2^-22 rel, << argmin gap)
// ---------------------------------------------------------------------------
__global__ __launch_bounds__(256, 2) void vq_hmma_kernel(const float* __restrict__ adj)
{
    extern __shared__ __align__(16) char smem[];
    unsigned long long* sRed = reinterpret_cast<unsigned long long*>(smem + SRED_OFF);
    const uint32_t sbase = smem_u32(smem);

    const int tid    = threadIdx.x;
    const int lane   = tid & 31;
    const int wid    = tid >> 5;
    const int warp_m = wid & 1;       // 0..1  (64 rows)
    const int warp_n = wid >> 1;      // 0..3  (32 cols)
    const int m0     = blockIdx.x * BLK_M;

#pragma unroll
    for (int i = 0; i < 8; i++) sRed[tid + 256 * i] = ~0ULL;

    int prev8[8];
#pragma unroll
    for (int mi = 0; mi < 4; mi++)
#pragma unroll
        for (int h = 0; h < 2; h++)
            prev8[mi * 2 + h] = g_prev[m0 + warp_m * 64 + mi * 16 + (lane >> 2) + h * 8];

    float acc[4][4][4];
#pragma unroll
    for (int mi = 0; mi < 4; mi++)
#pragma unroll
        for (int ni = 0; ni < 4; ni++)
#pragma unroll
            for (int e = 0; e < 4; e++) acc[mi][ni][e] = 0.f;

    // prologue: stages 0,1
    stage_cp(sbase, 0, m0, 0, tid); CP_COMMIT();
    stage_cp(sbase, 1, m0, 1, tid); CP_COMMIT();

    // fragment addressing
    const int arow8 = ((lane >> 3) & 1) * 8 + (lane & 7);    // A ldmatrix row-in-16
    const int akoff = (lane >> 4) * 16;                      // A ldmatrix k half
    // B ldmatrix.x4: matrix q = lane>>3 -> (ni offset q>>1, k-half q&1)
    const int bq = lane >> 3, br = lane & 7;
    const int boffs = (bq >> 1) * 8 * 48 + br * 48 + (bq & 1) * 16;

    for (int s = 0; s < NSTAGES; s++) {
        CP_WAIT1();
        __syncthreads();
        if (s + 2 < NSTAGES) stage_cp(sbase, (s + 2) % 3, m0, s + 2, tid);
        CP_COMMIT();

        const uint32_t buf = sbase + (s % 3) * STAGE_BYTES;

        // B fragments via ldmatrix.x4: [split][ni][2]
        uint32_t bF[2][4][2];
#pragma unroll
        for (int sp = 0; sp < 2; sp++) {
            const uint32_t bb = buf + (2 + sp) * SPLIT_BYTES + (warp_n * 32) * 48 + boffs;
            uint32_t r0[4], r1[4];
            ldmatrix_x4(r0, bb);          // ni 0,1
            ldmatrix_x4(r1, bb + 16 * 48); // ni 2,3
            bF[sp][0][0] = r0[0]; bF[sp][0][1] = r0[1];
            bF[sp][1][0] = r0[2]; bF[sp][1][1] = r0[3];
            bF[sp][2][0] = r1[0]; bF[sp][2][1] = r1[1];
            bF[sp][3][0] = r1[2]; bF[sp][3][1] = r1[3];
        }

        // A split 0: terms a0b0 + a0b1
        {
            uint32_t aF[4][4];
#pragma unroll
            for (int mi = 0; mi < 4; mi++)
                ldmatrix_x4(aF[mi], buf + (warp_m * 64 + mi * 16 + arow8) * 48 + akoff);
#pragma unroll
            for (int mi = 0; mi < 4; mi++)
#pragma unroll
                for (int ni = 0; ni < 4; ni++) {
                    mma_f16(acc[mi][ni], aF[mi], bF[0][ni]);
                    mma_f16(acc[mi][ni], aF[mi], bF[1][ni]);
                }
        }
        // A split 1: term a1b0 only
        {
            uint32_t aF[4][4];
#pragma unroll
            for (int mi = 0; mi < 4; mi++)
                ldmatrix_x4(aF[mi], buf + SPLIT_BYTES
                            + (warp_m * 64 + mi * 16 + arow8) * 48 + akoff);
#pragma unroll
            for (int mi = 0; mi < 4; mi++)
#pragma unroll
                for (int ni = 0; ni < 4; ni++)
                    mma_f16(acc[mi][ni], aF[mi], bF[0][ni]);
        }

        // epilogue at end of each n-tile
        if ((s & 31) == 31) {
            const int n0 = (s >> 5) * BLK_N;
#pragma unroll
            for (int mi = 0; mi < 4; mi++) {
#pragma unroll
                for (int h = 0; h < 2; h++) {
                    const int r = warp_m * 64 + mi * 16 + (lane >> 2) + h * 8;
                    const float* arow = adj + (size_t)prev8[mi * 2 + h] * KCB;
                    unsigned long long b = ~0ULL;
#pragma unroll
                    for (int ni = 0; ni < 4; ni++) {
                        const int n = n0 + warp_n * 32 + ni * 8 + (lane & 3) * 2;
                        float2 g  = *reinterpret_cast<const float2*>(arow + n);
                        float2 cn = *reinterpret_cast<const float2*>(g_cnorm + n);
                        float s0 = cn.x - 2.0f * acc[mi][ni][h * 2 + 0] - sig08(g.x);
                        float s1 = cn.y - 2.0f * acc[mi][ni][h * 2 + 1] - sig08(g.y);
                        unsigned u0 = __float_as_uint(s0);
                        u0 = (u0 & 0x80000000u) ? ~u0 : (u0 | 0x80000000u);
                        unsigned u1 = __float_as_uint(s1);
                        u1 = (u1 & 0x80000000u) ? ~u1 : (u1 | 0x80000000u);
                        unsigned long long c0 = ((unsigned long long)u0 << 32) | (unsigned)n;
                        unsigned long long c1 = ((unsigned long long)u1 << 32) | (unsigned)(n + 1);
                        b = (c0 < b) ? c0 : b;
                        b = (c1 < b) ? c1 : b;
                    }
                    unsigned long long* slot = &sRed[r * 16 + warp_n * 4 + (lane & 3)];
                    if (b < *slot) *slot = b;   // single-owner slot
                }
            }
#pragma unroll
            for (int mi = 0; mi < 4; mi++)
#pragma unroll
                for (int ni = 0; ni < 4; ni++)
#pragma unroll
                    for (int e = 0; e < 4; e++) acc[mi][ni][e] = 0.f;
        }
    }

    __syncthreads();
    if (tid < BLK_M) {
        unsigned long long b = sRed[tid * 16];
#pragma unroll
        for (int t = 1; t < 16; t++) {
            unsigned long long c = sRed[tid * 16 + t];
            b = (c < b) ? c : b;
        }
        g_idx[m0 + tid] = (int)(b & 0xffffffffu);
    }
}

// ---------------------------------------------------------------------------
// Kernel 4: gather z_q = codebook[idx], write outputs, per-row squared error
// ---------------------------------------------------------------------------
__global__ void gather_kernel(const float* __restrict__ zr,
                              const float* __restrict__ zi,
                              const float* __restrict__ cb,
                              float* __restrict__ out)
{
    __shared__ float sw[4];
    const int row = blockIdx.x;
    const int tid = threadIdx.x;
    const int idx = g_idx[row];
    const int j   = tid * 4;

    float4 c = *reinterpret_cast<const float4*>(cb + (size_t)idx * D2 + j);
    float4 z;
    float* o;
    if (j < DHALF) {
        z = *reinterpret_cast<const float4*>(zr + (size_t)row * DHALF + j);
        o = out + OUT_REAL_OFF + (size_t)row * DHALF + j;
    } else {
        z = *reinterpret_cast<const float4*>(zi + (size_t)row * DHALF + (j - DHALF));
        o = out + OUT_IMAG_OFF + (size_t)row * DHALF + (j - DHALF);
    }
    *reinterpret_cast<float4*>(o) = c;

    float dx = c.x - z.x, dy = c.y - z.y, dz = c.z - z.z, dw = c.w - z.w;
    float s = dx * dx + dy * dy + dz * dz + dw * dw;
#pragma unroll
    for (int of = 16; of; of >>= 1) s += __shfl_xor_sync(0xffffffffu, s, of);
    if ((tid & 31) == 0) sw[tid >> 5] = s;
    __syncthreads();
    if (tid == 0) {
        g_rowsum[row] = sw[0] + sw[1] + sw[2] + sw[3];
        out[OUT_IDX_OFF + row] = (float)idx;
    }
}

// ---------------------------------------------------------------------------
// Kernel 5: deterministic final loss reduction
// ---------------------------------------------------------------------------
__global__ void loss_kernel(float* __restrict__ out) {
    __shared__ float sm[1024];
    const int tid = threadIdx.x;
    float s = 0.f;
#pragma unroll 1
    for (int k = 0; k < 32; k++) s += g_rowsum[tid + 1024 * k];
    sm[tid] = s;
    __syncthreads();
    for (int off = 512; off; off >>= 1) {
        if (tid < off) sm[tid] += sm[tid + off];
        __syncthreads();
    }
    if (tid == 0) out[OUT_LOSS_OFF] = sm[0] * (1.01f / 16777216.0f);
}

// ---------------------------------------------------------------------------
extern "C" void kernel_launch(void* const* d_in, const int* in_sizes, int n_in,
                              void* d_out, int out_size) {
    const float* zr   = (const float*)d_in[0];
    const float* zi   = (const float*)d_in[1];
    const void*  prev = d_in[2];
    const float* cb   = (const float*)d_in[3];
    const float* adj  = (const float*)d_in[4];
    float* out = (float*)d_out;

    cudaFuncSetAttribute(vq_hmma_kernel,
                         cudaFuncAttributeMaxDynamicSharedMemorySize, SMEM_TOTAL);

    prev_kernel<<<(M_TOTAL + 255) / 256, 256>>>(prev);
    cnorm_kernel<<<KCB / 8, 256>>>(cb);
    split_kernel<<<(M_TOTAL * D2 / 4) / 256 + (KCB * D2 / 4) / 256, 256>>>(zr, zi, cb);
    vq_hmma_kernel<<<M_TOTAL / BLK_M, 256, SMEM_TOTAL>>>(adj);   // launch #4 -> ncu
    gather_kernel<<<M_TOTAL, 128>>>(zr, zi, cb, out);
    loss_kernel<<<1, 1024>>>(out);
}

// round 12
// speedup vs baseline: 1.3588x; 1.0878x over previous
#include <cuda_runtime.h>
#include <cuda_fp16.h>
#include <cstdint>

#define M_TOTAL 32768
#define DHALF   256
#define D2      512
#define KCB     4096

#define BLK_M 128
#define BLK_N 128
#define NCELLS 8192                 // 256 m-tiles x 32 n-tiles

// smem: per split tile 128 rows x 48B (16 fp16 = 32B data + 16B pad)
#define SPLIT_BYTES 6144
#define STAGE_BYTES (4 * SPLIT_BYTES)            // A0,A1,B0,B1 = 24576
#define SRED_OFF    (3 * STAGE_BYTES)            // 73728 (3-deep ring)
#define SMEM_TOTAL  (SRED_OFF + BLK_M * 16 * 8)  // + 16KB keys = 90112

#define OUT_REAL_OFF 0
#define OUT_IMAG_OFF 8388608
#define OUT_LOSS_OFF 16777216
#define OUT_IDX_OFF  16777217

__device__ __align__(16) float g_cnorm[KCB];
__device__ int   g_prev[M_TOTAL];
__device__ float g_rowsum[M_TOTAL];
__device__ unsigned long long g_key[M_TOTAL];   // (score-bits << 32) | idx
__device__ int   g_work;                         // work-steal counter
// 2-way fp16 splits, K-major [row][k 0..511]
__device__ __align__(16) __half g_zh[2][(size_t)M_TOTAL * D2];
__device__ __align__(16) __half g_ch[2][(size_t)KCB * D2];

// ---------------------------------------------------------------------------
__device__ __forceinline__ uint32_t smem_u32(const void* p) {
    uint32_t a;
    asm("{ .reg .u64 t; cvta.to.shared.u64 t, %1; cvt.u32.u64 %0, t; }"
        : "=r"(a) : "l"(p));
    return a;
}

__device__ __forceinline__ void cp16(uint32_t dst, const void* src) {
    asm volatile("cp.async.cg.shared.global [%0], [%1], 16;"
                 :: "r"(dst), "l"(src) : "memory");
}
#define CP_COMMIT() asm volatile("cp.async.commit_group;" ::: "memory")
#define CP_WAIT1()  asm volatile("cp.async.wait_group 1;" ::: "memory")

__device__ __forceinline__ void ldmatrix_x4(uint32_t* r, uint32_t addr) {
    asm volatile("ldmatrix.sync.aligned.m8n8.x4.shared.b16 {%0,%1,%2,%3}, [%4];"
                 : "=r"(r[0]), "=r"(r[1]), "=r"(r[2]), "=r"(r[3]) : "r"(addr));
}

__device__ __forceinline__ void mma_f16(float* d, const uint32_t* a,
                                        const uint32_t* b) {
    asm volatile(
        "mma.sync.aligned.m16n8k16.row.col.f32.f16.f16.f32 "
        "{%0,%1,%2,%3},{%4,%5,%6,%7},{%8,%9},{%0,%1,%2,%3};"
        : "+f"(d[0]), "+f"(d[1]), "+f"(d[2]), "+f"(d[3])
        : "r"(a[0]), "r"(a[1]), "r"(a[2]), "r"(a[3]), "r"(b[0]), "r"(b[1]));
}

// exact 2-way fp16 split: v = h0 + h1 (to ~2^-22 rel)
__device__ __forceinline__ void split2(float v, unsigned short& s0,
                                       unsigned short& s1) {
    __half h0 = __float2half_rn(v);
    __half h1 = __float2half_rn(v - __half2float(h0));
    s0 = __half_as_ushort(h0);
    s1 = __half_as_ushort(h1);
}

__device__ __forceinline__ float sig08(float x) {
    float x2 = x * x;
    // 0.8*sigmoid(x) = 0.4 + 0.8*x*p(x^2), odd Taylor to x^9 (|x| <= 1)
    float p = 2.1356922e-05f;
    p = fmaf(p, x2, -2.1081349e-04f);
    p = fmaf(p, x2,  2.0833334e-03f);
    p = fmaf(p, x2, -2.0833333e-02f);
    p = fmaf(p, x2,  0.25f);
    float s = fmaf(0.8f * x, p, 0.4f);
    if (fabsf(x) > 1.0f) s = 0.8f / (1.0f + __expf(-x));
    return s;
}

// ---------------------------------------------------------------------------
// Kernel 0: normalize prev_symbol_idx; reset work counter + global keys
// ---------------------------------------------------------------------------
__global__ void prev_kernel(const void* __restrict__ p) {
    const long long* p64 = (const long long*)p;
    const int*       p32 = (const int*)p;
    bool is64 = true;
    for (int t = 0; t < 64; t++) {
        long long v = p64[t];
        if (v < 0 || v >= KCB) { is64 = false; break; }
    }
    int i = blockIdx.x * blockDim.x + threadIdx.x;
    if (i < M_TOTAL) {
        g_prev[i] = is64 ? (int)p64[i] : p32[i];
        g_key[i]  = ~0ULL;
    }
    if (i == 0) g_work = 0;
}

// ---------------------------------------------------------------------------
// Kernel 1: cnorm[k] = ||codebook[k]||^2 (exact, f32)
// ---------------------------------------------------------------------------
__global__ void cnorm_kernel(const float* __restrict__ cb) {
    int warp = (blockIdx.x * blockDim.x + threadIdx.x) >> 5;
    int lane = threadIdx.x & 31;
    if (warp >= KCB) return;
    const float4* row = reinterpret_cast<const float4*>(cb + (size_t)warp * D2);
    float s = 0.f;
#pragma unroll
    for (int w = 0; w < 4; w++) {
        float4 v = row[lane + 32 * w];
        s += v.x * v.x + v.y * v.y + v.z * v.z + v.w * v.w;
    }
#pragma unroll
    for (int o = 16; o; o >>= 1) s += __shfl_xor_sync(0xffffffffu, s, o);
    if (lane == 0) g_cnorm[warp] = s;
}

// ---------------------------------------------------------------------------
// Kernel 2 (merged): f32 -> 2x fp16 slices for both z and codebook
// ---------------------------------------------------------------------------
__global__ void split_kernel(const float* __restrict__ zr,
                             const float* __restrict__ zi,
                             const float* __restrict__ cb) {
    const int zblocks = (M_TOTAL * D2 / 4) / 256;   // 16384
    float4 v;
    __half* d0;
    __half* d1;
    if (blockIdx.x < zblocks) {
        int g  = blockIdx.x * 256 + threadIdx.x;
        int m  = g >> 7;
        int k4 = (g & 127) * 4;
        v = (k4 < DHALF)
            ? *reinterpret_cast<const float4*>(zr + (size_t)m * DHALF + k4)
            : *reinterpret_cast<const float4*>(zi + (size_t)m * DHALF + (k4 - DHALF));
        size_t off = (size_t)m * D2 + k4;
        d0 = &g_zh[0][off]; d1 = &g_zh[1][off];
    } else {
        int g = (blockIdx.x - zblocks) * 256 + threadIdx.x;
        size_t off = (size_t)g * 4;
        v = *reinterpret_cast<const float4*>(cb + off);
        d0 = &g_ch[0][off]; d1 = &g_ch[1][off];
    }
    ushort4 o0, o1;
    split2(v.x, o0.x, o1.x);
    split2(v.y, o0.y, o1.y);
    split2(v.z, o0.z, o1.z);
    split2(v.w, o0.w, o1.w);
    *reinterpret_cast<ushort4*>(d0) = o0;
    *reinterpret_cast<ushort4*>(d1) = o1;
}

// ---------------------------------------------------------------------------
// cp.async one k16-stage for cell (am0, bn0) at k-base kb into ring slot
// ---------------------------------------------------------------------------
__device__ __forceinline__ void stage_cp(uint32_t sbase, int slot, int am0,
                                         int bn0, int kb, int tid) {
    const int row = tid >> 1, h = tid & 1;
    const uint32_t d = sbase + slot * STAGE_BYTES + row * 48 + h * 16;
    const size_t aoff = (size_t)(am0 + row) * D2 + kb + h * 8;
    const size_t boff = (size_t)(bn0 + row) * D2 + kb + h * 8;
    cp16(d,                   &g_zh[0][aoff]);
    cp16(d + SPLIT_BYTES,     &g_zh[1][aoff]);
    cp16(d + 2 * SPLIT_BYTES, &g_ch[0][boff]);
    cp16(d + 3 * SPLIT_BYTES, &g_ch[1][boff]);
}

// ---------------------------------------------------------------------------
// Kernel 3: persistent work-stolen HMMA fp16 3-term GEMM + bias + argmin.
// Cell = (m-tile, n-tile) with full K. Inner loop identical to R8/R11.
// Keys merge to g_key via u64 atomicMin (order-independent, tie-break exact).
// ---------------------------------------------------------------------------
__global__ __launch_bounds__(256, 2) void vq_hmma_kernel(const float* __restrict__ adj)
{
    extern __shared__ __align__(16) char smem[];
    __shared__ int sCell[2];
    unsigned long long* sRed = reinterpret_cast<unsigned long long*>(smem + SRED_OFF);
    const uint32_t sbase = smem_u32(smem);

    const int tid    = threadIdx.x;
    const int lane   = tid & 31;
    const int wid    = tid >> 5;
    const int warp_m = wid & 1;       // 0..1  (64 rows)
    const int warp_n = wid >> 1;      // 0..3  (32 cols)

#pragma unroll
    for (int i = 0; i < 8; i++) sRed[tid + 256 * i] = ~0ULL;

    if (tid == 0) sCell[0] = atomicAdd(&g_work, 1);
    __syncthreads();
    int cur = sCell[0];
    int rs  = 0;                      // ring slot of next computed stage

    if (cur < NCELLS) {
        const int am0 = (cur >> 5) * BLK_M, bn0 = (cur & 31) * BLK_N;
        stage_cp(sbase, 0, am0, bn0, 0,  tid); CP_COMMIT();
        stage_cp(sbase, 1, am0, bn0, 16, tid); CP_COMMIT();
    }

    float acc[4][4][4];
#pragma unroll
    for (int mi = 0; mi < 4; mi++)
#pragma unroll
        for (int ni = 0; ni < 4; ni++)
#pragma unroll
            for (int e = 0; e < 4; e++) acc[mi][ni][e] = 0.f;

    // fragment addressing
    const int arow8 = ((lane >> 3) & 1) * 8 + (lane & 7);    // A ldmatrix row-in-16
    const int akoff = (lane >> 4) * 16;                      // A ldmatrix k half
    const int bq = lane >> 3, br = lane & 7;
    const int boffs = (bq >> 1) * 8 * 48 + br * 48 + (bq & 1) * 16;

    while (cur < NCELLS) {
        const int am0 = (cur >> 5) * BLK_M;
        const int n0  = (cur & 31) * BLK_N;

        for (int s = 0; s < 32; s++) {
            CP_WAIT1();
            __syncthreads();
            if (s == 26 && tid == 0) sCell[1] = atomicAdd(&g_work, 1);
            if (s < 30) {
                stage_cp(sbase, (rs + 2) % 3, am0, n0, (s + 2) * 16, tid);
            } else {
                const int nx = sCell[1];   // written s==26, barriers since
                if (nx < NCELLS)
                    stage_cp(sbase, (rs + 2) % 3, (nx >> 5) * BLK_M,
                             (nx & 31) * BLK_N, (s - 30) * 16, tid);
            }
            CP_COMMIT();

            const uint32_t buf = sbase + rs * STAGE_BYTES;

            // B fragments via ldmatrix.x4: [split][ni][2]
            uint32_t bF[2][4][2];
#pragma unroll
            for (int sp = 0; sp < 2; sp++) {
                const uint32_t bb = buf + (2 + sp) * SPLIT_BYTES
                                  + (warp_n * 32) * 48 + boffs;
                uint32_t r0[4], r1[4];
                ldmatrix_x4(r0, bb);           // ni 0,1
                ldmatrix_x4(r1, bb + 16 * 48); // ni 2,3
                bF[sp][0][0] = r0[0]; bF[sp][0][1] = r0[1];
                bF[sp][1][0] = r0[2]; bF[sp][1][1] = r0[3];
                bF[sp][2][0] = r1[0]; bF[sp][2][1] = r1[1];
                bF[sp][3][0] = r1[2]; bF[sp][3][1] = r1[3];
            }
            // A split 0: terms a0b0 + a0b1
            {
                uint32_t aF[4][4];
#pragma unroll
                for (int mi = 0; mi < 4; mi++)
                    ldmatrix_x4(aF[mi], buf + (warp_m * 64 + mi * 16 + arow8) * 48 + akoff);
#pragma unroll
                for (int mi = 0; mi < 4; mi++)
#pragma unroll
                    for (int ni = 0; ni < 4; ni++) {
                        mma_f16(acc[mi][ni], aF[mi], bF[0][ni]);
                        mma_f16(acc[mi][ni], aF[mi], bF[1][ni]);
                    }
            }
            // A split 1: term a1b0 only
            {
                uint32_t aF[4][4];
#pragma unroll
                for (int mi = 0; mi < 4; mi++)
                    ldmatrix_x4(aF[mi], buf + SPLIT_BYTES
                                + (warp_m * 64 + mi * 16 + arow8) * 48 + akoff);
#pragma unroll
                for (int mi = 0; mi < 4; mi++)
#pragma unroll
                    for (int ni = 0; ni < 4; ni++)
                        mma_f16(acc[mi][ni], aF[mi], bF[0][ni]);
            }

            // epilogue at end of cell
            if (s == 31) {
#pragma unroll
                for (int mi = 0; mi < 4; mi++) {
#pragma unroll
                    for (int h = 0; h < 2; h++) {
                        const int r = warp_m * 64 + mi * 16 + (lane >> 2) + h * 8;
                        const float* arow = adj + (size_t)g_prev[am0 + r] * KCB;
                        unsigned long long b = ~0ULL;
#pragma unroll
                        for (int ni = 0; ni < 4; ni++) {
                            const int n = n0 + warp_n * 32 + ni * 8 + (lane & 3) * 2;
                            float2 g  = *reinterpret_cast<const float2*>(arow + n);
                            float2 cn = *reinterpret_cast<const float2*>(g_cnorm + n);
                            float s0 = cn.x - 2.0f * acc[mi][ni][h * 2 + 0] - sig08(g.x);
                            float s1 = cn.y - 2.0f * acc[mi][ni][h * 2 + 1] - sig08(g.y);
                            unsigned u0 = __float_as_uint(s0);
                            u0 = (u0 & 0x80000000u) ? ~u0 : (u0 | 0x80000000u);
                            unsigned u1 = __float_as_uint(s1);
                            u1 = (u1 & 0x80000000u) ? ~u1 : (u1 | 0x80000000u);
                            unsigned long long c0 = ((unsigned long long)u0 << 32) | (unsigned)n;
                            unsigned long long c1 = ((unsigned long long)u1 << 32) | (unsigned)(n + 1);
                            b = (c0 < b) ? c0 : b;
                            b = (c1 < b) ? c1 : b;
                        }
                        unsigned long long* slot = &sRed[r * 16 + warp_n * 4 + (lane & 3)];
                        if (b < *slot) *slot = b;   // single-owner slot
                    }
                }
#pragma unroll
                for (int mi = 0; mi < 4; mi++)
#pragma unroll
                    for (int ni = 0; ni < 4; ni++)
#pragma unroll
                        for (int e = 0; e < 4; e++) acc[mi][ni][e] = 0.f;
            }
            rs = (rs == 2) ? 0 : rs + 1;
        }

        const int nxt = sCell[1];
        const bool flush = (nxt >= NCELLS) || (((nxt >> 5) * BLK_M) != am0);
        if (flush) {
            __syncthreads();           // epilogue slot writes visible
            if (tid < BLK_M) {
                unsigned long long b = sRed[tid * 16];
#pragma unroll
                for (int t = 1; t < 16; t++) {
                    unsigned long long c = sRed[tid * 16 + t];
                    b = (c < b) ? c : b;
                }
                atomicMin(&g_key[am0 + tid], b);
#pragma unroll
                for (int t = 0; t < 16; t++) sRed[tid * 16 + t] = ~0ULL;
            }
            // next sRed writes are >=32 barriers away; no extra sync needed
        }
        cur = nxt;
    }
}

// ---------------------------------------------------------------------------
// Kernel 4: gather z_q = codebook[idx], write outputs, per-row squared error
// ---------------------------------------------------------------------------
__global__ void gather_kernel(const float* __restrict__ zr,
                              const float* __restrict__ zi,
                              const float* __restrict__ cb,
                              float* __restrict__ out)
{
    __shared__ float sw[4];
    const int row = blockIdx.x;
    const int tid = threadIdx.x;
    const int idx = (int)(g_key[row] & 0xffffffffu);
    const int j   = tid * 4;

    float4 c = *reinterpret_cast<const float4*>(cb + (size_t)idx * D2 + j);
    float4 z;
    float* o;
    if (j < DHALF) {
        z = *reinterpret_cast<const float4*>(zr + (size_t)row * DHALF + j);
        o = out + OUT_REAL_OFF + (size_t)row * DHALF + j;
    } else {
        z = *reinterpret_cast<const float4*>(zi + (size_t)row * DHALF + (j - DHALF));
        o = out + OUT_IMAG_OFF + (size_t)row * DHALF + (j - DHALF);
    }
    *reinterpret_cast<float4*>(o) = c;

    float dx = c.x - z.x, dy = c.y - z.y, dz = c.z - z.z, dw = c.w - z.w;
    float s = dx * dx + dy * dy + dz * dz + dw * dw;
#pragma unroll
    for (int of = 16; of; of >>= 1) s += __shfl_xor_sync(0xffffffffu, s, of);
    if ((tid & 31) == 0) sw[tid >> 5] = s;
    __syncthreads();
    if (tid == 0) {
        g_rowsum[row] = sw[0] + sw[1] + sw[2] + sw[3];
        out[OUT_IDX_OFF + row] = (float)idx;
    }
}

// ---------------------------------------------------------------------------
// Kernel 5: deterministic final loss reduction
// ---------------------------------------------------------------------------
__global__ void loss_kernel(float* __restrict__ out) {
    __shared__ float sm[1024];
    const int tid = threadIdx.x;
    float s = 0.f;
#pragma unroll 1
    for (int k = 0; k < 32; k++) s += g_rowsum[tid + 1024 * k];
    sm[tid] = s;
    __syncthreads();
    for (int off = 512; off; off >>= 1) {
        if (tid < off) sm[tid] += sm[tid + off];
        __syncthreads();
    }
    if (tid == 0) out[OUT_LOSS_OFF] = sm[0] * (1.01f / 16777216.0f);
}

// ---------------------------------------------------------------------------
extern "C" void kernel_launch(void* const* d_in, const int* in_sizes, int n_in,
                              void* d_out, int out_size) {
    const float* zr   = (const float*)d_in[0];
    const float* zi   = (const float*)d_in[1];
    const void*  prev = d_in[2];
    const float* cb   = (const float*)d_in[3];
    const float* adj  = (const float*)d_in[4];
    float* out = (float*)d_out;

    cudaFuncSetAttribute(vq_hmma_kernel,
                         cudaFuncAttributeMaxDynamicSharedMemorySize, SMEM_TOTAL);

    int dev = 0, nsm = 148;
    cudaGetDevice(&dev);
    cudaDeviceGetAttribute(&nsm, cudaDevAttrMultiProcessorCount, dev);
    int grid = 2 * nsm;
    if (grid > NCELLS) grid = NCELLS;

    prev_kernel<<<(M_TOTAL + 255) / 256, 256>>>(prev);
    cnorm_kernel<<<KCB / 8, 256>>>(cb);
    split_kernel<<<(M_TOTAL * D2 / 4) / 256 + (KCB * D2 / 4) / 256, 256>>>(zr, zi, cb);
    vq_hmma_kernel<<<grid, 256, SMEM_TOTAL>>>(adj);   // launch #4 -> ncu
    gather_kernel<<<M_TOTAL, 128>>>(zr, zi, cb, out);
    loss_kernel<<<1, 1024>>>(out);
}

// round 13
// speedup vs baseline: 1.3591x; 1.0002x over previous
#include <cuda_runtime.h>
#include <cuda_fp16.h>
#include <cstdint>

#define M_TOTAL 32768
#define DHALF   256
#define D2      512
#define KCB     4096

#define BLK_M 128
#define BLK_N 128
#define NCELLS 8192                 // 256 m-tiles x 32 n-tiles

// smem: per split tile 128 rows x 48B (16 fp16 = 32B data + 16B pad)
#define SPLIT_BYTES 6144
#define STAGE_BYTES (4 * SPLIT_BYTES)            // A0,A1,B0,B1 = 24576
#define SRED_OFF    (3 * STAGE_BYTES)            // 73728 (3-deep ring)
#define SMEM_TOTAL  (SRED_OFF + BLK_M * 16 * 8)  // + 16KB keys = 90112

#define OUT_REAL_OFF 0
#define OUT_IMAG_OFF 8388608
#define OUT_LOSS_OFF 16777216
#define OUT_IDX_OFF  16777217

__device__ __align__(16) float g_cnorm[KCB];
__device__ int   g_prev[M_TOTAL];
__device__ float g_rowsum[M_TOTAL];
__device__ unsigned long long g_key[M_TOTAL];   // (score-bits << 32) | idx
__device__ int   g_work;                         // work-steal counter
// 2-way fp16 splits, K-major [row][k 0..511]
__device__ __align__(16) __half g_zh[2][(size_t)M_TOTAL * D2];
__device__ __align__(16) __half g_ch[2][(size_t)KCB * D2];

// ---------------------------------------------------------------------------
__device__ __forceinline__ uint32_t smem_u32(const void* p) {
    uint32_t a;
    asm("{ .reg .u64 t; cvta.to.shared.u64 t, %1; cvt.u32.u64 %0, t; }"
        : "=r"(a) : "l"(p));
    return a;
}

__device__ __forceinline__ void cp16(uint32_t dst, const void* src) {
    asm volatile("cp.async.cg.shared.global [%0], [%1], 16;"
                 :: "r"(dst), "l"(src) : "memory");
}
#define CP_COMMIT() asm volatile("cp.async.commit_group;" ::: "memory")
#define CP_WAIT1()  asm volatile("cp.async.wait_group 1;" ::: "memory")

__device__ __forceinline__ void ldmatrix_x4(uint32_t* r, uint32_t addr) {
    asm volatile("ldmatrix.sync.aligned.m8n8.x4.shared.b16 {%0,%1,%2,%3}, [%4];"
                 : "=r"(r[0]), "=r"(r[1]), "=r"(r[2]), "=r"(r[3]) : "r"(addr));
}

__device__ __forceinline__ void mma_f16(float* d, const uint32_t* a,
                                        const uint32_t* b) {
    asm volatile(
        "mma.sync.aligned.m16n8k16.row.col.f32.f16.f16.f32 "
        "{%0,%1,%2,%3},{%4,%5,%6,%7},{%8,%9},{%0,%1,%2,%3};"
        : "+f"(d[0]), "+f"(d[1]), "+f"(d[2]), "+f"(d[3])
        : "r"(a[0]), "r"(a[1]), "r"(a[2]), "r"(a[3]), "r"(b[0]), "r"(b[1]));
}

// exact 2-way fp16 split: v = h0 + h1 (to ~2^-22 rel)
__device__ __forceinline__ void split2(float v, unsigned short& s0,
                                       unsigned short& s1) {
    __half h0 = __float2half_rn(v);
    __half h1 = __float2half_rn(v - __half2float(h0));
    s0 = __half_as_ushort(h0);
    s1 = __half_as_ushort(h1);
}

__device__ __forceinline__ float sig08(float x) {
    float x2 = x * x;
    // 0.8*sigmoid(x) = 0.4 + 0.8*x*p(x^2), odd Taylor to x^9 (|x| <= 1)
    float p = 2.1356922e-05f;
    p = fmaf(p, x2, -2.1081349e-04f);
    p = fmaf(p, x2,  2.0833334e-03f);
    p = fmaf(p, x2, -2.0833333e-02f);
    p = fmaf(p, x2,  0.25f);
    float s = fmaf(0.8f * x, p, 0.4f);
    if (fabsf(x) > 1.0f) s = 0.8f / (1.0f + __expf(-x));
    return s;
}

// ---------------------------------------------------------------------------
// Kernel 0: normalize prev_symbol_idx; reset work counter + global keys
// ---------------------------------------------------------------------------
__global__ void prev_kernel(const void* __restrict__ p) {
    const long long* p64 = (const long long*)p;
    const int*       p32 = (const int*)p;
    bool is64 = true;
    for (int t = 0; t < 64; t++) {
        long long v = p64[t];
        if (v < 0 || v >= KCB) { is64 = false; break; }
    }
    int i = blockIdx.x * blockDim.x + threadIdx.x;
    if (i < M_TOTAL) {
        g_prev[i] = is64 ? (int)p64[i] : p32[i];
        g_key[i]  = ~0ULL;
    }
    if (i == 0) g_work = 0;
}

// ---------------------------------------------------------------------------
// Kernel 1: cnorm[k] = ||codebook[k]||^2 (exact, f32)
// ---------------------------------------------------------------------------
__global__ void cnorm_kernel(const float* __restrict__ cb) {
    int warp = (blockIdx.x * blockDim.x + threadIdx.x) >> 5;
    int lane = threadIdx.x & 31;
    if (warp >= KCB) return;
    const float4* row = reinterpret_cast<const float4*>(cb + (size_t)warp * D2);
    float s = 0.f;
#pragma unroll
    for (int w = 0; w < 4; w++) {
        float4 v = row[lane + 32 * w];
        s += v.x * v.x + v.y * v.y + v.z * v.z + v.w * v.w;
    }
#pragma unroll
    for (int o = 16; o; o >>= 1) s += __shfl_xor_sync(0xffffffffu, s, o);
    if (lane == 0) g_cnorm[warp] = s;
}

// ---------------------------------------------------------------------------
// Kernel 2 (merged): f32 -> 2x fp16 slices for both z and codebook
// ---------------------------------------------------------------------------
__global__ void split_kernel(const float* __restrict__ zr,
                             const float* __restrict__ zi,
                             const float* __restrict__ cb) {
    const int zblocks = (M_TOTAL * D2 / 4) / 256;   // 16384
    float4 v;
    __half* d0;
    __half* d1;
    if (blockIdx.x < zblocks) {
        int g  = blockIdx.x * 256 + threadIdx.x;
        int m  = g >> 7;
        int k4 = (g & 127) * 4;
        v = (k4 < DHALF)
            ? *reinterpret_cast<const float4*>(zr + (size_t)m * DHALF + k4)
            : *reinterpret_cast<const float4*>(zi + (size_t)m * DHALF + (k4 - DHALF));
        size_t off = (size_t)m * D2 + k4;
        d0 = &g_zh[0][off]; d1 = &g_zh[1][off];
    } else {
        int g = (blockIdx.x - zblocks) * 256 + threadIdx.x;
        size_t off = (size_t)g * 4;
        v = *reinterpret_cast<const float4*>(cb + off);
        d0 = &g_ch[0][off]; d1 = &g_ch[1][off];
    }
    ushort4 o0, o1;
    split2(v.x, o0.x, o1.x);
    split2(v.y, o0.y, o1.y);
    split2(v.z, o0.z, o1.z);
    split2(v.w, o0.w, o1.w);
    *reinterpret_cast<ushort4*>(d0) = o0;
    *reinterpret_cast<ushort4*>(d1) = o1;
}

// ---------------------------------------------------------------------------
// cp.async one k16-stage for cell (am0, bn0) at k-base kb into ring slot
// ---------------------------------------------------------------------------
__device__ __forceinline__ void stage_cp(uint32_t sbase, int slot, int am0,
                                         int bn0, int kb, int tid) {
    const int row = tid >> 1, h = tid & 1;
    const uint32_t d = sbase + slot * STAGE_BYTES + row * 48 + h * 16;
    const size_t aoff = (size_t)(am0 + row) * D2 + kb + h * 8;
    const size_t boff = (size_t)(bn0 + row) * D2 + kb + h * 8;
    cp16(d,                   &g_zh[0][aoff]);
    cp16(d + SPLIT_BYTES,     &g_zh[1][aoff]);
    cp16(d + 2 * SPLIT_BYTES, &g_ch[0][boff]);
    cp16(d + 3 * SPLIT_BYTES, &g_ch[1][boff]);
}

// ---------------------------------------------------------------------------
// Kernel 3: persistent work-stolen HMMA fp16 3-term GEMM + bias + argmin.
// Cell = (m-tile, n-tile) with full K. MMA section issued as three
// independent 16-MMA sweeps (no same-accumulator RAW within a sweep).
// ---------------------------------------------------------------------------
__global__ __launch_bounds__(256, 2) void vq_hmma_kernel(const float* __restrict__ adj)
{
    extern __shared__ __align__(16) char smem[];
    __shared__ int sCell[2];
    unsigned long long* sRed = reinterpret_cast<unsigned long long*>(smem + SRED_OFF);
    const uint32_t sbase = smem_u32(smem);

    const int tid    = threadIdx.x;
    const int lane   = tid & 31;
    const int wid    = tid >> 5;
    const int warp_m = wid & 1;       // 0..1  (64 rows)
    const int warp_n = wid >> 1;      // 0..3  (32 cols)

#pragma unroll
    for (int i = 0; i < 8; i++) sRed[tid + 256 * i] = ~0ULL;

    if (tid == 0) sCell[0] = atomicAdd(&g_work, 1);
    __syncthreads();
    int cur = sCell[0];
    int rs  = 0;                      // ring slot of next computed stage

    if (cur < NCELLS) {
        const int am0 = (cur >> 5) * BLK_M, bn0 = (cur & 31) * BLK_N;
        stage_cp(sbase, 0, am0, bn0, 0,  tid); CP_COMMIT();
        stage_cp(sbase, 1, am0, bn0, 16, tid); CP_COMMIT();
    }

    float acc[4][4][4];
#pragma unroll
    for (int mi = 0; mi < 4; mi++)
#pragma unroll
        for (int ni = 0; ni < 4; ni++)
#pragma unroll
            for (int e = 0; e < 4; e++) acc[mi][ni][e] = 0.f;

    // fragment addressing
    const int arow8 = ((lane >> 3) & 1) * 8 + (lane & 7);    // A ldmatrix row-in-16
    const int akoff = (lane >> 4) * 16;                      // A ldmatrix k half
    const int bq = lane >> 3, br = lane & 7;
    const int boffs = (bq >> 1) * 8 * 48 + br * 48 + (bq & 1) * 16;

    while (cur < NCELLS) {
        const int am0 = (cur >> 5) * BLK_M;
        const int n0  = (cur & 31) * BLK_N;

        for (int s = 0; s < 32; s++) {
            CP_WAIT1();
            __syncthreads();
            if (s == 26 && tid == 0) sCell[1] = atomicAdd(&g_work, 1);
            if (s < 30) {
                stage_cp(sbase, (rs + 2) % 3, am0, n0, (s + 2) * 16, tid);
            } else {
                const int nx = sCell[1];   // written s==26, barriers since
                if (nx < NCELLS)
                    stage_cp(sbase, (rs + 2) % 3, (nx >> 5) * BLK_M,
                             (nx & 31) * BLK_N, (s - 30) * 16, tid);
            }
            CP_COMMIT();

            const uint32_t buf = sbase + rs * STAGE_BYTES;

            // B fragments via ldmatrix.x4: [split][ni][2]
            uint32_t bF[2][4][2];
#pragma unroll
            for (int sp = 0; sp < 2; sp++) {
                const uint32_t bb = buf + (2 + sp) * SPLIT_BYTES
                                  + (warp_n * 32) * 48 + boffs;
                uint32_t r0[4], r1[4];
                ldmatrix_x4(r0, bb);           // ni 0,1
                ldmatrix_x4(r1, bb + 16 * 48); // ni 2,3
                bF[sp][0][0] = r0[0]; bF[sp][0][1] = r0[1];
                bF[sp][1][0] = r0[2]; bF[sp][1][1] = r0[3];
                bF[sp][2][0] = r1[0]; bF[sp][2][1] = r1[1];
                bF[sp][3][0] = r1[2]; bF[sp][3][1] = r1[3];
            }
            // A split-0 fragments
            uint32_t aF[4][4];
#pragma unroll
            for (int mi = 0; mi < 4; mi++)
                ldmatrix_x4(aF[mi], buf + (warp_m * 64 + mi * 16 + arow8) * 48 + akoff);

            // pass 1: a0*b0 — 16 independent MMAs
#pragma unroll
            for (int mi = 0; mi < 4; mi++)
#pragma unroll
                for (int ni = 0; ni < 4; ni++)
                    mma_f16(acc[mi][ni], aF[mi], bF[0][ni]);
            // pass 2: a0*b1 — same accs, >=16 instructions since last touch
#pragma unroll
            for (int mi = 0; mi < 4; mi++)
#pragma unroll
                for (int ni = 0; ni < 4; ni++)
                    mma_f16(acc[mi][ni], aF[mi], bF[1][ni]);
            // A split-1 fragments (LDSM latency hidden under pass 2)
            uint32_t aG[4][4];
#pragma unroll
            for (int mi = 0; mi < 4; mi++)
                ldmatrix_x4(aG[mi], buf + SPLIT_BYTES
                            + (warp_m * 64 + mi * 16 + arow8) * 48 + akoff);
            // pass 3: a1*b0
#pragma unroll
            for (int mi = 0; mi < 4; mi++)
#pragma unroll
                for (int ni = 0; ni < 4; ni++)
                    mma_f16(acc[mi][ni], aG[mi], bF[0][ni]);

            // epilogue at end of cell
            if (s == 31) {
#pragma unroll
                for (int mi = 0; mi < 4; mi++) {
#pragma unroll
                    for (int h = 0; h < 2; h++) {
                        const int r = warp_m * 64 + mi * 16 + (lane >> 2) + h * 8;
                        const float* arow = adj + (size_t)g_prev[am0 + r] * KCB;
                        unsigned long long b = ~0ULL;
#pragma unroll
                        for (int ni = 0; ni < 4; ni++) {
                            const int n = n0 + warp_n * 32 + ni * 8 + (lane & 3) * 2;
                            float2 g  = *reinterpret_cast<const float2*>(arow + n);
                            float2 cn = *reinterpret_cast<const float2*>(g_cnorm + n);
                            float s0 = cn.x - 2.0f * acc[mi][ni][h * 2 + 0] - sig08(g.x);
                            float s1 = cn.y - 2.0f * acc[mi][ni][h * 2 + 1] - sig08(g.y);
                            unsigned u0 = __float_as_uint(s0);
                            u0 = (u0 & 0x80000000u) ? ~u0 : (u0 | 0x80000000u);
                            unsigned u1 = __float_as_uint(s1);
                            u1 = (u1 & 0x80000000u) ? ~u1 : (u1 | 0x80000000u);
                            unsigned long long c0 = ((unsigned long long)u0 << 32) | (unsigned)n;
                            unsigned long long c1 = ((unsigned long long)u1 << 32) | (unsigned)(n + 1);
                            b = (c0 < b) ? c0 : b;
                            b = (c1 < b) ? c1 : b;
                        }
                        unsigned long long* slot = &sRed[r * 16 + warp_n * 4 + (lane & 3)];
                        if (b < *slot) *slot = b;   // single-owner slot
                    }
                }
#pragma unroll
                for (int mi = 0; mi < 4; mi++)
#pragma unroll
                    for (int ni = 0; ni < 4; ni++)
#pragma unroll
                        for (int e = 0; e < 4; e++) acc[mi][ni][e] = 0.f;
            }
            rs = (rs == 2) ? 0 : rs + 1;
        }

        const int nxt = sCell[1];
        const bool flush = (nxt >= NCELLS) || (((nxt >> 5) * BLK_M) != am0);
        if (flush) {
            __syncthreads();           // epilogue slot writes visible
            if (tid < BLK_M) {
                unsigned long long b = sRed[tid * 16];
#pragma unroll
                for (int t = 1; t < 16; t++) {
                    unsigned long long c = sRed[tid * 16 + t];
                    b = (c < b) ? c : b;
                }
                atomicMin(&g_key[am0 + tid], b);
#pragma unroll
                for (int t = 0; t < 16; t++) sRed[tid * 16 + t] = ~0ULL;
            }
            // next sRed writes are >=32 barriers away; no extra sync needed
        }
        cur = nxt;
    }
}

// ---------------------------------------------------------------------------
// Kernel 4: gather z_q = codebook[idx], write outputs, per-row squared error
// ---------------------------------------------------------------------------
__global__ void gather_kernel(const float* __restrict__ zr,
                              const float* __restrict__ zi,
                              const float* __restrict__ cb,
                              float* __restrict__ out)
{
    __shared__ float sw[4];
    const int row = blockIdx.x;
    const int tid = threadIdx.x;
    const int idx = (int)(g_key[row] & 0xffffffffu);
    const int j   = tid * 4;

    float4 c = *reinterpret_cast<const float4*>(cb + (size_t)idx * D2 + j);
    float4 z;
    float* o;
    if (j < DHALF) {
        z = *reinterpret_cast<const float4*>(zr + (size_t)row * DHALF + j);
        o = out + OUT_REAL_OFF + (size_t)row * DHALF + j;
    } else {
        z = *reinterpret_cast<const float4*>(zi + (size_t)row * DHALF + (j - DHALF));
        o = out + OUT_IMAG_OFF + (size_t)row * DHALF + (j - DHALF);
    }
    *reinterpret_cast<float4*>(o) = c;

    float dx = c.x - z.x, dy = c.y - z.y, dz = c.z - z.z, dw = c.w - z.w;
    float s = dx * dx + dy * dy + dz * dz + dw * dw;
#pragma unroll
    for (int of = 16; of; of >>= 1) s += __shfl_xor_sync(0xffffffffu, s, of);
    if ((tid & 31) == 0) sw[tid >> 5] = s;
    __syncthreads();
    if (tid == 0) {
        g_rowsum[row] = sw[0] + sw[1] + sw[2] + sw[3];
        out[OUT_IDX_OFF + row] = (float)idx;
    }
}

// ---------------------------------------------------------------------------
// Kernel 5: deterministic final loss reduction
// ---------------------------------------------------------------------------
__global__ void loss_kernel(float* __restrict__ out) {
    __shared__ float sm[1024];
    const int tid = threadIdx.x;
    float s = 0.f;
#pragma unroll 1
    for (int k = 0; k < 32; k++) s += g_rowsum[tid + 1024 * k];
    sm[tid] = s;
    __syncthreads();
    for (int off = 512; off; off >>= 1) {
        if (tid < off) sm[tid] += sm[tid + off];
        __syncthreads();
    }
    if (tid == 0) out[OUT_LOSS_OFF] = sm[0] * (1.01f / 16777216.0f);
}

// ---------------------------------------------------------------------------
extern "C" void kernel_launch(void* const* d_in, const int* in_sizes, int n_in,
                              void* d_out, int out_size) {
    const float* zr   = (const float*)d_in[0];
    const float* zi   = (const float*)d_in[1];
    const void*  prev = d_in[2];
    const float* cb   = (const float*)d_in[3];
    const float* adj  = (const float*)d_in[4];
    float* out = (float*)d_out;

    cudaFuncSetAttribute(vq_hmma_kernel,
                         cudaFuncAttributeMaxDynamicSharedMemorySize, SMEM_TOTAL);

    int dev = 0, nsm = 148;
    cudaGetDevice(&dev);
    cudaDeviceGetAttribute(&nsm, cudaDevAttrMultiProcessorCount, dev);
    int grid = 2 * nsm;
    if (grid > NCELLS) grid = NCELLS;

    prev_kernel<<<(M_TOTAL + 255) / 256, 256>>>(prev);
    cnorm_kernel<<<KCB / 8, 256>>>(cb);
    split_kernel<<<(M_TOTAL * D2 / 4) / 256 + (KCB * D2 / 4) / 256, 256>>>(zr, zi, cb);
    vq_hmma_kernel<<<grid, 256, SMEM_TOTAL>>>(adj);   // launch #4 -> ncu
    gather_kernel<<<M_TOTAL, 128>>>(zr, zi, cb, out);
    loss_kernel<<<1, 1024>>>(out);
}

// round 14
// speedup vs baseline: 2.3717x; 1.7451x over previous
#include <cuda_runtime.h>
#include <cuda_fp16.h>
#include <cstdint>

#define M_TOTAL 32768
#define DHALF   256
#define D2      512
#define KCB     4096

#define BLK_M 128
#define BLK_N 128
#define NCELLS 8192                 // 256 m-tiles x 32 n-tiles
#define MARGIN 1.25f                // > 2x hard screening error bound

// smem: per tile 128 rows x 48B (16 fp16 = 32B data + 16B pad)
#define TILE_BYTES  6144
#define STAGE_BYTES (2 * TILE_BYTES)   // A, B = 12288
#define SMEM_TOTAL  (3 * STAGE_BYTES)  // 3-deep ring = 36864

#define OUT_REAL_OFF 0
#define OUT_IMAG_OFF 8388608
#define OUT_LOSS_OFF 16777216
#define OUT_IDX_OFF  16777217

__device__ __align__(16) float g_cnorm[KCB];
__device__ int   g_prev[M_TOTAL];
__device__ int   g_idx[M_TOTAL];
__device__ float g_rowsum[M_TOTAL];
__device__ int   g_work;                         // work-steal counter
// fp16-rounded inputs (K-major) and screened scores
__device__ __align__(16) __half g_zh[(size_t)M_TOTAL * D2];
__device__ __align__(16) __half g_ch[(size_t)KCB * D2];
__device__ __align__(16) __half g_scores[(size_t)M_TOTAL * KCB];

// ---------------------------------------------------------------------------
__device__ __forceinline__ uint32_t smem_u32(const void* p) {
    uint32_t a;
    asm("{ .reg .u64 t; cvta.to.shared.u64 t, %1; cvt.u32.u64 %0, t; }"
        : "=r"(a) : "l"(p));
    return a;
}

__device__ __forceinline__ void cp16(uint32_t dst, const void* src) {
    asm volatile("cp.async.cg.shared.global [%0], [%1], 16;"
                 :: "r"(dst), "l"(src) : "memory");
}
#define CP_COMMIT() asm volatile("cp.async.commit_group;" ::: "memory")
#define CP_WAIT1()  asm volatile("cp.async.wait_group 1;" ::: "memory")

__device__ __forceinline__ void ldmatrix_x4(uint32_t* r, uint32_t addr) {
    asm volatile("ldmatrix.sync.aligned.m8n8.x4.shared.b16 {%0,%1,%2,%3}, [%4];"
                 : "=r"(r[0]), "=r"(r[1]), "=r"(r[2]), "=r"(r[3]) : "r"(addr));
}

__device__ __forceinline__ void mma_f16(float* d, const uint32_t* a,
                                        const uint32_t* b) {
    asm volatile(
        "mma.sync.aligned.m16n8k16.row.col.f32.f16.f16.f32 "
        "{%0,%1,%2,%3},{%4,%5,%6,%7},{%8,%9},{%0,%1,%2,%3};"
        : "+f"(d[0]), "+f"(d[1]), "+f"(d[2]), "+f"(d[3])
        : "r"(a[0]), "r"(a[1]), "r"(a[2]), "r"(a[3]), "r"(b[0]), "r"(b[1]));
}

__device__ __forceinline__ float sig08(float x) {
    float x2 = x * x;
    // 0.8*sigmoid(x) = 0.4 + 0.8*x*p(x^2), odd Taylor to x^9 (|x| <= 1)
    float p = 2.1356922e-05f;
    p = fmaf(p, x2, -2.1081349e-04f);
    p = fmaf(p, x2,  2.0833334e-03f);
    p = fmaf(p, x2, -2.0833333e-02f);
    p = fmaf(p, x2,  0.25f);
    float s = fmaf(0.8f * x, p, 0.4f);
    if (fabsf(x) > 1.0f) s = 0.8f / (1.0f + __expf(-x));
    return s;
}

__device__ __forceinline__ unsigned long long score_key(float s, int n) {
    unsigned u = __float_as_uint(s);
    u = (u & 0x80000000u) ? ~u : (u | 0x80000000u);   // order-preserving
    return ((unsigned long long)u << 32) | (unsigned)n;
}

// ---------------------------------------------------------------------------
// Kernel 0: normalize prev_symbol_idx; reset work counter
// ---------------------------------------------------------------------------
__global__ void prev_kernel(const void* __restrict__ p) {
    const long long* p64 = (const long long*)p;
    const int*       p32 = (const int*)p;
    bool is64 = true;
    for (int t = 0; t < 64; t++) {
        long long v = p64[t];
        if (v < 0 || v >= KCB) { is64 = false; break; }
    }
    int i = blockIdx.x * blockDim.x + threadIdx.x;
    if (i < M_TOTAL) g_prev[i] = is64 ? (int)p64[i] : p32[i];
    if (i == 0) g_work = 0;
}

// ---------------------------------------------------------------------------
// Kernel 1: cnorm[k] = ||codebook[k]||^2 (exact, f32)
// ---------------------------------------------------------------------------
__global__ void cnorm_kernel(const float* __restrict__ cb) {
    int warp = (blockIdx.x * blockDim.x + threadIdx.x) >> 5;
    int lane = threadIdx.x & 31;
    if (warp >= KCB) return;
    const float4* row = reinterpret_cast<const float4*>(cb + (size_t)warp * D2);
    float s = 0.f;
#pragma unroll
    for (int w = 0; w < 4; w++) {
        float4 v = row[lane + 32 * w];
        s += v.x * v.x + v.y * v.y + v.z * v.z + v.w * v.w;
    }
#pragma unroll
    for (int o = 16; o; o >>= 1) s += __shfl_xor_sync(0xffffffffu, s, o);
    if (lane == 0) g_cnorm[warp] = s;
}

// ---------------------------------------------------------------------------
// Kernel 2: f32 -> fp16 (single rounding) for z and codebook
// ---------------------------------------------------------------------------
__global__ void split_kernel(const float* __restrict__ zr,
                             const float* __restrict__ zi,
                             const float* __restrict__ cb) {
    const int zblocks = (M_TOTAL * D2 / 4) / 256;   // 16384
    float4 v;
    __half* d0;
    if (blockIdx.x < zblocks) {
        int g  = blockIdx.x * 256 + threadIdx.x;
        int m  = g >> 7;
        int k4 = (g & 127) * 4;
        v = (k4 < DHALF)
            ? *reinterpret_cast<const float4*>(zr + (size_t)m * DHALF + k4)
            : *reinterpret_cast<const float4*>(zi + (size_t)m * DHALF + (k4 - DHALF));
        d0 = &g_zh[(size_t)m * D2 + k4];
    } else {
        int g = (blockIdx.x - zblocks) * 256 + threadIdx.x;
        v = *reinterpret_cast<const float4*>(cb + (size_t)g * 4);
        d0 = &g_ch[(size_t)g * 4];
    }
    ushort4 o;
    o.x = __half_as_ushort(__float2half_rn(v.x));
    o.y = __half_as_ushort(__float2half_rn(v.y));
    o.z = __half_as_ushort(__float2half_rn(v.z));
    o.w = __half_as_ushort(__float2half_rn(v.w));
    *reinterpret_cast<ushort4*>(d0) = o;
}

// ---------------------------------------------------------------------------
// cp.async one k16-stage (A,B tiles, 128 rows x 32B each); 2 x 16B per thread
// ---------------------------------------------------------------------------
__device__ __forceinline__ void stage_cp(uint32_t sbase, int slot, int am0,
                                         int bn0, int kb, int tid) {
    const int row = tid >> 1, h = tid & 1;
    const uint32_t d = sbase + slot * STAGE_BYTES + row * 48 + h * 16;
    cp16(d,              &g_zh[(size_t)(am0 + row) * D2 + kb + h * 8]);
    cp16(d + TILE_BYTES, &g_ch[(size_t)(bn0 + row) * D2 + kb + h * 8]);
}

// ---------------------------------------------------------------------------
// Kernel 3: persistent work-stolen fp16 SCREENING GEMM (1 term) + bias;
// stores fp16 scores to g_scores. No argmin here.
// ---------------------------------------------------------------------------
__global__ __launch_bounds__(256, 2) void vq_screen_kernel(const float* __restrict__ adj)
{
    extern __shared__ __align__(16) char smem[];
    __shared__ int sCell[2];
    const uint32_t sbase = smem_u32(smem);

    const int tid    = threadIdx.x;
    const int lane   = tid & 31;
    const int wid    = tid >> 5;
    const int warp_m = wid & 1;       // 0..1  (64 rows)
    const int warp_n = wid >> 1;      // 0..3  (32 cols)

    if (tid == 0) sCell[0] = atomicAdd(&g_work, 1);
    __syncthreads();
    int cur = sCell[0];
    int rs  = 0;

    if (cur < NCELLS) {
        const int am0 = (cur >> 5) * BLK_M, bn0 = (cur & 31) * BLK_N;
        stage_cp(sbase, 0, am0, bn0, 0,  tid); CP_COMMIT();
        stage_cp(sbase, 1, am0, bn0, 16, tid); CP_COMMIT();
    }

    float acc[4][4][4];
#pragma unroll
    for (int mi = 0; mi < 4; mi++)
#pragma unroll
        for (int ni = 0; ni < 4; ni++)
#pragma unroll
            for (int e = 0; e < 4; e++) acc[mi][ni][e] = 0.f;

    const int arow8 = ((lane >> 3) & 1) * 8 + (lane & 7);
    const int akoff = (lane >> 4) * 16;
    const int bq = lane >> 3, br = lane & 7;
    const int boffs = (bq >> 1) * 8 * 48 + br * 48 + (bq & 1) * 16;

    while (cur < NCELLS) {
        const int am0 = (cur >> 5) * BLK_M;
        const int n0  = (cur & 31) * BLK_N;

        for (int s = 0; s < 32; s++) {
            CP_WAIT1();
            __syncthreads();
            if (s == 26 && tid == 0) sCell[1] = atomicAdd(&g_work, 1);
            if (s < 30) {
                stage_cp(sbase, (rs + 2) % 3, am0, n0, (s + 2) * 16, tid);
            } else {
                const int nx = sCell[1];
                if (nx < NCELLS)
                    stage_cp(sbase, (rs + 2) % 3, (nx >> 5) * BLK_M,
                             (nx & 31) * BLK_N, (s - 30) * 16, tid);
            }
            CP_COMMIT();

            const uint32_t buf = sbase + rs * STAGE_BYTES;

            // B fragments (2 x ldmatrix.x4)
            uint32_t bF[4][2];
            {
                const uint32_t bb = buf + TILE_BYTES + (warp_n * 32) * 48 + boffs;
                uint32_t r0[4], r1[4];
                ldmatrix_x4(r0, bb);
                ldmatrix_x4(r1, bb + 16 * 48);
                bF[0][0] = r0[0]; bF[0][1] = r0[1];
                bF[1][0] = r0[2]; bF[1][1] = r0[3];
                bF[2][0] = r1[0]; bF[2][1] = r1[1];
                bF[3][0] = r1[2]; bF[3][1] = r1[3];
            }
            // A fragments
            uint32_t aF[4][4];
#pragma unroll
            for (int mi = 0; mi < 4; mi++)
                ldmatrix_x4(aF[mi], buf + (warp_m * 64 + mi * 16 + arow8) * 48 + akoff);

            // 16 independent MMAs
#pragma unroll
            for (int mi = 0; mi < 4; mi++)
#pragma unroll
                for (int ni = 0; ni < 4; ni++)
                    mma_f16(acc[mi][ni], aF[mi], bF[ni]);

            // epilogue at end of cell: compute + store fp16 scores
            if (s == 31) {
#pragma unroll
                for (int mi = 0; mi < 4; mi++) {
#pragma unroll
                    for (int h = 0; h < 2; h++) {
                        const int r = warp_m * 64 + mi * 16 + (lane >> 2) + h * 8;
                        const float* arow = adj + (size_t)g_prev[am0 + r] * KCB;
                        __half* srow = &g_scores[(size_t)(am0 + r) * KCB];
#pragma unroll
                        for (int ni = 0; ni < 4; ni++) {
                            const int n = n0 + warp_n * 32 + ni * 8 + (lane & 3) * 2;
                            float2 g  = *reinterpret_cast<const float2*>(arow + n);
                            float2 cn = *reinterpret_cast<const float2*>(g_cnorm + n);
                            float s0 = cn.x - 2.0f * acc[mi][ni][h * 2 + 0] - sig08(g.x);
                            float s1 = cn.y - 2.0f * acc[mi][ni][h * 2 + 1] - sig08(g.y);
                            *reinterpret_cast<__half2*>(srow + n) =
                                __floats2half2_rn(s0, s1);
                        }
                    }
                }
#pragma unroll
                for (int mi = 0; mi < 4; mi++)
#pragma unroll
                    for (int ni = 0; ni < 4; ni++)
#pragma unroll
                        for (int e = 0; e < 4; e++) acc[mi][ni][e] = 0.f;
            }
            rs = (rs == 2) ? 0 : rs + 1;
        }
        cur = sCell[1];
    }
}

// ---------------------------------------------------------------------------
// Kernel 4: per-row filter + exact fp32 rescore -> g_idx
// One 128-thread block per row.
// ---------------------------------------------------------------------------
__global__ __launch_bounds__(128) void filter_kernel(
    const float* __restrict__ zr, const float* __restrict__ zi,
    const float* __restrict__ cb, const float* __restrict__ adj)
{
    __shared__ float zsh[D2];
    __shared__ int   cand[1024];
    __shared__ int   ccount;
    __shared__ float red[4];
    __shared__ float rowmin_sh;

    const int row  = blockIdx.x;
    const int tid  = threadIdx.x;
    const int lane = tid & 31;
    const int wrp  = tid >> 5;

    // load z row (f32 exact)
    {
        int j = tid * 4;
        float4 v = (j < DHALF)
            ? *reinterpret_cast<const float4*>(zr + (size_t)row * DHALF + j)
            : *reinterpret_cast<const float4*>(zi + (size_t)row * DHALF + (j - DHALF));
        *reinterpret_cast<float4*>(&zsh[j]) = v;
    }
    if (tid == 0) ccount = 0;

    // load this thread's 32 scores (64B contiguous)
    const __half* srow = &g_scores[(size_t)row * KCB];
    uint4 raw[4];
#pragma unroll
    for (int i = 0; i < 4; i++)
        raw[i] = *reinterpret_cast<const uint4*>(srow + tid * 32 + i * 8);
    const __half2* h2 = reinterpret_cast<const __half2*>(raw);

    float smin = 1e30f;
#pragma unroll
    for (int i = 0; i < 16; i++) {
        float2 f = __half22float2(h2[i]);
        smin = fminf(smin, fminf(f.x, f.y));
    }
#pragma unroll
    for (int o = 16; o; o >>= 1)
        smin = fminf(smin, __shfl_xor_sync(0xffffffffu, smin, o));
    if (lane == 0) red[wrp] = smin;
    __syncthreads();
    if (tid == 0)
        rowmin_sh = fminf(fminf(red[0], red[1]), fminf(red[2], red[3]));
    __syncthreads();

    const float thr = rowmin_sh + MARGIN;
#pragma unroll
    for (int i = 0; i < 16; i++) {
        float2 f = __half22float2(h2[i]);
        if (f.x <= thr) { int p = atomicAdd(&ccount, 1); if (p < 1024) cand[p] = tid * 32 + i * 2; }
        if (f.y <= thr) { int p = atomicAdd(&ccount, 1); if (p < 1024) cand[p] = tid * 32 + i * 2 + 1; }
    }
    __syncthreads();

    const int cnt = (ccount < 1024) ? ccount : 1024;
    unsigned long long best = ~0ULL;
    const int myprev = g_prev[row];

    for (int i = 0; i < cnt; i++) {
        const int n = cand[i];
        float4 cv = reinterpret_cast<const float4*>(cb + (size_t)n * D2)[tid];
        const int j = tid * 4;
        float d = zsh[j] * cv.x + zsh[j + 1] * cv.y
                + zsh[j + 2] * cv.z + zsh[j + 3] * cv.w;
#pragma unroll
        for (int o = 16; o; o >>= 1) d += __shfl_xor_sync(0xffffffffu, d, o);
        if (lane == 0) red[wrp] = d;
        __syncthreads();
        if (tid == 0) {
            float dot = red[0] + red[1] + red[2] + red[3];
            float s = g_cnorm[n] - 2.0f * dot
                    - sig08(adj[(size_t)myprev * KCB + n]);
            unsigned long long k = score_key(s, n);
            best = (k < best) ? k : best;
        }
        __syncthreads();
    }
    if (tid == 0) g_idx[row] = (int)(best & 0xffffffffu);
}

// ---------------------------------------------------------------------------
// Kernel 5: gather z_q = codebook[idx], write outputs, per-row squared error
// ---------------------------------------------------------------------------
__global__ void gather_kernel(const float* __restrict__ zr,
                              const float* __restrict__ zi,
                              const float* __restrict__ cb,
                              float* __restrict__ out)
{
    __shared__ float sw[4];
    const int row = blockIdx.x;
    const int tid = threadIdx.x;
    const int idx = g_idx[row];
    const int j   = tid * 4;

    float4 c = *reinterpret_cast<const float4*>(cb + (size_t)idx * D2 + j);
    float4 z;
    float* o;
    if (j < DHALF) {
        z = *reinterpret_cast<const float4*>(zr + (size_t)row * DHALF + j);
        o = out + OUT_REAL_OFF + (size_t)row * DHALF + j;
    } else {
        z = *reinterpret_cast<const float4*>(zi + (size_t)row * DHALF + (j - DHALF));
        o = out + OUT_IMAG_OFF + (size_t)row * DHALF + (j - DHALF);
    }
    *reinterpret_cast<float4*>(o) = c;

    float dx = c.x - z.x, dy = c.y - z.y, dz = c.z - z.z, dw = c.w - z.w;
    float s = dx * dx + dy * dy + dz * dz + dw * dw;
#pragma unroll
    for (int of = 16; of; of >>= 1) s += __shfl_xor_sync(0xffffffffu, s, of);
    if ((tid & 31) == 0) sw[tid >> 5] = s;
    __syncthreads();
    if (tid == 0) {
        g_rowsum[row] = sw[0] + sw[1] + sw[2] + sw[3];
        out[OUT_IDX_OFF + row] = (float)idx;
    }
}

// ---------------------------------------------------------------------------
// Kernel 6: deterministic final loss reduction
// ---------------------------------------------------------------------------
__global__ void loss_kernel(float* __restrict__ out) {
    __shared__ float sm[1024];
    const int tid = threadIdx.x;
    float s = 0.f;
#pragma unroll 1
    for (int k = 0; k < 32; k++) s += g_rowsum[tid + 1024 * k];
    sm[tid] = s;
    __syncthreads();
    for (int off = 512; off; off >>= 1) {
        if (tid < off) sm[tid] += sm[tid + off];
        __syncthreads();
    }
    if (tid == 0) out[OUT_LOSS_OFF] = sm[0] * (1.01f / 16777216.0f);
}

// ---------------------------------------------------------------------------
extern "C" void kernel_launch(void* const* d_in, const int* in_sizes, int n_in,
                              void* d_out, int out_size) {
    const float* zr   = (const float*)d_in[0];
    const float* zi   = (const float*)d_in[1];
    const void*  prev = d_in[2];
    const float* cb   = (const float*)d_in[3];
    const float* adj  = (const float*)d_in[4];
    float* out = (float*)d_out;

    cudaFuncSetAttribute(vq_screen_kernel,
                         cudaFuncAttributeMaxDynamicSharedMemorySize, SMEM_TOTAL);

    int dev = 0, nsm = 148;
    cudaGetDevice(&dev);
    cudaDeviceGetAttribute(&nsm, cudaDevAttrMultiProcessorCount, dev);
    int grid = 2 * nsm;
    if (grid > NCELLS) grid = NCELLS;

    prev_kernel<<<(M_TOTAL + 255) / 256, 256>>>(prev);
    cnorm_kernel<<<KCB / 8, 256>>>(cb);
    split_kernel<<<(M_TOTAL * D2 / 4) / 256 + (KCB * D2 / 4) / 256, 256>>>(zr, zi, cb);
    vq_screen_kernel<<<grid, 256, SMEM_TOTAL>>>(adj);   // launch #4 -> ncu
    filter_kernel<<<M_TOTAL, 128>>>(zr, zi, cb, adj);
    gather_kernel<<<M_TOTAL, 128>>>(zr, zi, cb, out);
    loss_kernel<<<1, 1024>>>(out);
}